// round 10
// baseline (speedup 1.0000x reference)
#include <cuda_runtime.h>
#include <cuda_bf16.h>
#include <cstdint>

#define BB 4
#define SS 1024
#define DD 1024
#define HH 16
#define HD 64
#define NEGV -10000000.0f

// ---------------------------------------------------------------------------
// Scratch (__device__ globals; no allocation allowed)
// ---------------------------------------------------------------------------
__device__ float g_v[BB*HH*SS*HD];                 // V fp32 (pre-transpose)
__device__ unsigned g_mask[BB*SS*(SS/32)];
__device__ __nv_bfloat16 g_xhi[BB*SS*DD];
__device__ __nv_bfloat16 g_xlo[BB*SS*DD];
__device__ __nv_bfloat16 g_whi[3][DD*DD];          // transposed: [n][k]
__device__ __nv_bfloat16 g_wlo[3][DD*DD];
__device__ __nv_bfloat16 g_qhi[BB*HH*SS*HD];       // [b,h,s,hd]
__device__ __nv_bfloat16 g_qlo[BB*HH*SS*HD];
__device__ __nv_bfloat16 g_khi[BB*HH*SS*HD];       // [b,h,s,hd]
__device__ __nv_bfloat16 g_klo[BB*HH*SS*HD];
__device__ __nv_bfloat16 g_vthi[BB*HH*HD*SS];      // [b,h,hd,s]  (transposed)
__device__ __nv_bfloat16 g_vtlo[BB*HH*HD*SS];

// ---------------------------------------------------------------------------
// PTX helpers (baseline PTX only — works on plain sm_103 target)
// ---------------------------------------------------------------------------
__device__ __forceinline__ void mma16816(
    float& d0, float& d1, float& d2, float& d3,
    uint32_t a0, uint32_t a1, uint32_t a2, uint32_t a3,
    uint32_t b0, uint32_t b1)
{
    asm volatile(
        "mma.sync.aligned.m16n8k16.row.col.f32.bf16.bf16.f32 "
        "{%0,%1,%2,%3}, {%4,%5,%6,%7}, {%8,%9}, {%0,%1,%2,%3};"
        : "+f"(d0), "+f"(d1), "+f"(d2), "+f"(d3)
        : "r"(a0), "r"(a1), "r"(a2), "r"(a3), "r"(b0), "r"(b1));
}

__device__ __forceinline__ void ldm_x4(
    uint32_t& r0, uint32_t& r1, uint32_t& r2, uint32_t& r3, uint32_t addr)
{
    asm volatile("ldmatrix.sync.aligned.m8n8.x4.shared.b16 {%0,%1,%2,%3}, [%4];"
        : "=r"(r0), "=r"(r1), "=r"(r2), "=r"(r3) : "r"(addr));
}

__device__ __forceinline__ uint32_t smem_u32(const void* p) {
    uint32_t a;
    asm("{ .reg .u64 t; cvta.to.shared.u64 t, %1; cvt.u32.u64 %0, t; }"
        : "=r"(a) : "l"(p));
    return a;
}

__device__ __forceinline__ void cp16(uint32_t dst, const void* src) {
    asm volatile("cp.async.cg.shared.global [%0], [%1], 16;" :: "r"(dst), "l"(src));
}
#define CP_COMMIT() asm volatile("cp.async.commit_group;" ::: "memory")

// ---------------------------------------------------------------------------
// Prep: split x into bf16 hi/lo
// ---------------------------------------------------------------------------
__global__ __launch_bounds__(256) void conv_x(const float* __restrict__ x)
{
    size_t i = ((size_t)blockIdx.x * 256 + threadIdx.x) * 4;
    float4 v = *(const float4*)(x + i);
    __nv_bfloat16 h0 = __float2bfloat16(v.x);
    __nv_bfloat16 h1 = __float2bfloat16(v.y);
    __nv_bfloat16 h2 = __float2bfloat16(v.z);
    __nv_bfloat16 h3 = __float2bfloat16(v.w);
    __nv_bfloat16 l0 = __float2bfloat16(v.x - __bfloat162float(h0));
    __nv_bfloat16 l1 = __float2bfloat16(v.y - __bfloat162float(h1));
    __nv_bfloat16 l2 = __float2bfloat16(v.z - __bfloat162float(h2));
    __nv_bfloat16 l3 = __float2bfloat16(v.w - __bfloat162float(h3));
    __nv_bfloat162 p;
    p.x = h0; p.y = h1; *(__nv_bfloat162*)(g_xhi + i)     = p;
    p.x = h2; p.y = h3; *(__nv_bfloat162*)(g_xhi + i + 2) = p;
    p.x = l0; p.y = l1; *(__nv_bfloat162*)(g_xlo + i)     = p;
    p.x = l2; p.y = l3; *(__nv_bfloat162*)(g_xlo + i + 2) = p;
}

// ---------------------------------------------------------------------------
// Prep: transpose W [K,N] -> Wt [N,K], split hi/lo
// ---------------------------------------------------------------------------
__global__ __launch_bounds__(256) void conv_w(
    const float* __restrict__ Wq, const float* __restrict__ Wk, const float* __restrict__ Wv)
{
    const int z = blockIdx.z;
    const float* W = z == 0 ? Wq : (z == 1 ? Wk : Wv);
    __shared__ float t[32][33];
    int tx = threadIdx.x, ty = threadIdx.y;
    int n0 = blockIdx.x * 32, k0 = blockIdx.y * 32;
    #pragma unroll
    for (int r = 0; r < 4; r++) {
        int k = k0 + ty + r * 8;
        t[ty + r * 8][tx] = W[(size_t)k * DD + n0 + tx];
    }
    __syncthreads();
    #pragma unroll
    for (int r = 0; r < 4; r++) {
        int nn = n0 + ty + r * 8;
        int kk = k0 + tx;
        float v = t[tx][ty + r * 8];
        __nv_bfloat16 hi = __float2bfloat16(v);
        __nv_bfloat16 lo = __float2bfloat16(v - __bfloat162float(hi));
        g_whi[z][(size_t)nn * DD + kk] = hi;
        g_wlo[z][(size_t)nn * DD + kk] = lo;
    }
}

// ---------------------------------------------------------------------------
// QKV GEMM via mma.sync + 3-stage cp.async pipeline (single barrier/chunk).
// CTA 128x128, 8 warps (2Mx4N), warp tile 64x32, K-chunk 32.
// SMEM arrays: 128 rows x 32 bf16 (64 B/row), XOR-swizzled 16B chunks.
// 3 stages x 4 arrays x 8 KB = 96 KB  -> 2 CTAs/SM.
// ---------------------------------------------------------------------------
#define GT2   (128 * 32)
#define NSTG  3
#define GSMB  (NSTG * 4 * GT2 * 2)

__device__ __forceinline__ uint32_t gsw(int row, int chunk) {
    return (uint32_t)(row * 64 + ((chunk ^ ((row >> 1) & 3)) << 4));
}

__global__ __launch_bounds__(256, 2) void qkv_gemm_mma(
    const float* __restrict__ bq, const float* __restrict__ bk, const float* __restrict__ bv)
{
    extern __shared__ __nv_bfloat16 gsm[];

    const int tid  = threadIdx.x;
    const int lane = tid & 31;
    const int wid  = tid >> 5;
    const int wm   = wid >> 2;
    const int wn   = wid & 3;
    const int z    = blockIdx.z;
    const int m0   = blockIdx.y * 128;
    const int n0   = blockIdx.x * 128;

    const __nv_bfloat16* __restrict__ gAh = g_xhi;
    const __nv_bfloat16* __restrict__ gAl = g_xlo;
    const __nv_bfloat16* __restrict__ gBh = g_whi[z];
    const __nv_bfloat16* __restrict__ gBl = g_wlo[z];
    const float* bias = z == 0 ? bq : (z == 1 ? bk : bv);

    const uint32_t sb = smem_u32(gsm);

    float acc[4][4][4];
    #pragma unroll
    for (int mt = 0; mt < 4; mt++)
        #pragma unroll
        for (int nt = 0; nt < 4; nt++)
            #pragma unroll
            for (int r = 0; r < 4; r++) acc[mt][nt][r] = 0.f;

    const int fr = lane >> 2;
    const int fc = (lane & 3) * 2;

    auto issue_chunk = [&](int c) {
        const uint32_t base = sb + (uint32_t)((c % NSTG) * 4 * GT2) * 2;
        const int k0 = c * 32;
        #pragma unroll
        for (int i = 0; i < 2; i++) {
            const int idx = tid + i * 256;
            const int row = idx >> 2;
            const int seg = idx & 3;
            const uint32_t doff = gsw(row, seg);
            const size_t ao = (size_t)(m0 + row) * DD + k0 + seg * 8;
            const size_t bo = (size_t)(n0 + row) * DD + k0 + seg * 8;
            cp16(base + 0u * GT2 * 2 + doff, gAh + ao);
            cp16(base + 1u * GT2 * 2 + doff, gAl + ao);
            cp16(base + 2u * GT2 * 2 + doff, gBh + bo);
            cp16(base + 3u * GT2 * 2 + doff, gBl + bo);
        }
        CP_COMMIT();
    };

    issue_chunk(0);
    issue_chunk(1);

    for (int c = 0; c < 32; c++) {
        if (c < 30) asm volatile("cp.async.wait_group 1;" ::: "memory");
        else        asm volatile("cp.async.wait_group 0;" ::: "memory");
        __syncthreads();

        const uint32_t sbase = sb + (uint32_t)((c % NSTG) * 4 * GT2) * 2;
        #pragma unroll
        for (int ks = 0; ks < 2; ks++) {
            const int kc = ks * 2;
            uint32_t ah[4][4], al[4][4], bh[4][2], bl[4][2];
            #pragma unroll
            for (int mt = 0; mt < 4; mt++) {
                const int row = wm * 64 + mt * 16 + (lane & 15);
                const uint32_t aoff = gsw(row, kc + (lane >> 4));
                ldm_x4(ah[mt][0], ah[mt][1], ah[mt][2], ah[mt][3],
                       sbase + 0u * GT2 * 2 + aoff);
                ldm_x4(al[mt][0], al[mt][1], al[mt][2], al[mt][3],
                       sbase + 1u * GT2 * 2 + aoff);
            }
            #pragma unroll
            for (int np = 0; np < 2; np++) {
                const int row = wn * 32 + np * 16 + (lane & 7) + ((lane >> 4) << 3);
                const uint32_t boff = gsw(row, kc + ((lane >> 3) & 1));
                ldm_x4(bh[np * 2][0], bh[np * 2][1], bh[np * 2 + 1][0], bh[np * 2 + 1][1],
                       sbase + 2u * GT2 * 2 + boff);
                ldm_x4(bl[np * 2][0], bl[np * 2][1], bl[np * 2 + 1][0], bl[np * 2 + 1][1],
                       sbase + 3u * GT2 * 2 + boff);
            }
            #pragma unroll
            for (int mt = 0; mt < 4; mt++)
                #pragma unroll
                for (int nt = 0; nt < 4; nt++)
                    mma16816(acc[mt][nt][0], acc[mt][nt][1], acc[mt][nt][2], acc[mt][nt][3],
                             ah[mt][0], ah[mt][1], ah[mt][2], ah[mt][3],
                             bh[nt][0], bh[nt][1]);
            #pragma unroll
            for (int mt = 0; mt < 4; mt++)
                #pragma unroll
                for (int nt = 0; nt < 4; nt++)
                    mma16816(acc[mt][nt][0], acc[mt][nt][1], acc[mt][nt][2], acc[mt][nt][3],
                             ah[mt][0], ah[mt][1], ah[mt][2], ah[mt][3],
                             bl[nt][0], bl[nt][1]);
            #pragma unroll
            for (int mt = 0; mt < 4; mt++)
                #pragma unroll
                for (int nt = 0; nt < 4; nt++)
                    mma16816(acc[mt][nt][0], acc[mt][nt][1], acc[mt][nt][2], acc[mt][nt][3],
                             al[mt][0], al[mt][1], al[mt][2], al[mt][3],
                             bh[nt][0], bh[nt][1]);
        }

        if (c + 2 < 32) issue_chunk(c + 2);
    }

    __nv_bfloat16* ohi = z == 0 ? g_qhi : g_khi;
    __nv_bfloat16* olo = z == 0 ? g_qlo : g_klo;

    #pragma unroll
    for (int nt = 0; nt < 4; nt++) {
        const int n = n0 + wn * 32 + nt * 8 + fc;
        const int h = n >> 6;
        const int hd = n & 63;
        const float bv0 = bias[n];
        const float bv1 = bias[n + 1];
        #pragma unroll
        for (int mt = 0; mt < 4; mt++) {
            #pragma unroll
            for (int half = 0; half < 2; half++) {
                const int m = m0 + wm * 64 + mt * 16 + fr + half * 8;
                const int bb = m >> 10;
                const int s = m & 1023;
                float v0 = acc[mt][nt][half * 2 + 0] + bv0;
                float v1 = acc[mt][nt][half * 2 + 1] + bv1;
                size_t idx = ((size_t)(bb * HH + h) * SS + s) * HD + hd;
                if (z < 2) {
                    __nv_bfloat162 hv = __floats2bfloat162_rn(v0, v1);
                    __nv_bfloat162 lv = __floats2bfloat162_rn(
                        v0 - __bfloat162float(hv.x), v1 - __bfloat162float(hv.y));
                    *(__nv_bfloat162*)(ohi + idx) = hv;
                    *(__nv_bfloat162*)(olo + idx) = lv;
                } else {
                    float2 o; o.x = v0; o.y = v1;
                    *(float2*)(g_v + idx) = o;
                }
            }
        }
    }
}

// ---------------------------------------------------------------------------
// V: transpose [b,h,s,hd] f32 -> [b,h,hd,s] bf16 hi/lo
// ---------------------------------------------------------------------------
__global__ __launch_bounds__(256) void v_conv()
{
    __shared__ float t[32][33];
    const int bh = blockIdx.z;
    const int s0 = blockIdx.x * 32;
    const int hd0 = blockIdx.y * 32;
    const int tx = threadIdx.x, ty = threadIdx.y;
    #pragma unroll
    for (int r = 0; r < 4; r++) {
        int s = s0 + ty + r * 8;
        t[ty + r * 8][tx] = g_v[((size_t)bh * SS + s) * HD + hd0 + tx];
    }
    __syncthreads();
    #pragma unroll
    for (int r = 0; r < 4; r++) {
        int hd = hd0 + ty + r * 8;
        int s = s0 + tx;
        float v = t[tx][ty + r * 8];
        __nv_bfloat16 hi = __float2bfloat16(v);
        __nv_bfloat16 lo = __float2bfloat16(v - __bfloat162float(hi));
        g_vthi[((size_t)bh * HD + hd) * SS + s] = hi;
        g_vtlo[((size_t)bh * HD + hd) * SS + s] = lo;
    }
}

// ---------------------------------------------------------------------------
// Pack adj into 1-bit mask and copy adj to second output region.
// ---------------------------------------------------------------------------
__global__ __launch_bounds__(256) void mask_pack(
    const float* __restrict__ adj, float* __restrict__ adj_out)
{
    int w = blockIdx.x * blockDim.x + threadIdx.x;
    const float4* a4 = (const float4*)adj;
    float4* o4 = (float4*)adj_out;
    unsigned bits = 0;
    #pragma unroll
    for (int i = 0; i < 8; i++) {
        float4 v = a4[(size_t)w * 8 + i];
        o4[(size_t)w * 8 + i] = v;
        bits |= (v.x >= 0.5f ? 1u : 0u) << (i * 4 + 0);
        bits |= (v.y >= 0.5f ? 1u : 0u) << (i * 4 + 1);
        bits |= (v.z >= 0.5f ? 1u : 0u) << (i * 4 + 2);
        bits |= (v.w >= 0.5f ? 1u : 0u) << (i * 4 + 3);
    }
    g_mask[w] = bits;
}

// ---------------------------------------------------------------------------
// Flash attention via mma.sync: q-tile 128, 256 threads (8 warps x 16 rows),
// K/V tiles 64 double-buffered with cp.async. 2 CTAs/SM (108 KB smem).
// ---------------------------------------------------------------------------
#define AQP 72
#define KT_ELEM (64 * AQP)            // K/V tile array (64 rows)
#define QT_ELEM (128 * AQP)           // Q tile array (128 rows)

__global__ __launch_bounds__(256, 2) void attn_mma(float* __restrict__ out)
{
    extern __shared__ __nv_bfloat16 smp[];
    __nv_bfloat16* Qh = smp;                      // [128][AQP]
    __nv_bfloat16* Ql = Qh + QT_ELEM;
    __nv_bfloat16* KV = Ql + QT_ELEM;             // 2 stages x {Kh,Kl,Vh,Vl}

    const int tid  = threadIdx.x;
    const int lane = tid & 31;
    const int warp = tid >> 5;
    const int g    = lane >> 2;
    const int t    = lane & 3;
    const int q0   = blockIdx.x * 128;
    const int h    = blockIdx.y;
    const int bb   = blockIdx.z;
    const int wq0  = warp * 16;

    const size_t bhs = ((size_t)(bb * HH + h)) * SS;
    const __nv_bfloat16* gqh = g_qhi + (bhs + q0) * HD;
    const __nv_bfloat16* gql = g_qlo + (bhs + q0) * HD;
    const __nv_bfloat16* gkh = g_khi + bhs * HD;
    const __nv_bfloat16* gkl = g_klo + bhs * HD;
    const __nv_bfloat16* gvh = g_vthi + ((size_t)(bb * HH + h)) * HD * SS;
    const __nv_bfloat16* gvl = g_vtlo + ((size_t)(bb * HH + h)) * HD * SS;

    const uint32_t sQh = smem_u32(Qh);
    const uint32_t sQl = smem_u32(Ql);
    const uint32_t sKV = smem_u32(KV);

    // ---- issue Q (128 rows) + K/V tile 0 ----
    {
        #pragma unroll
        for (int j = 0; j < 4; j++) {
            int id  = tid + j * 256;          // 0..1023
            int r   = id >> 3;                // 0..127
            int seg = id & 7;
            uint32_t doff = (uint32_t)(r * AQP + seg * 8) * 2;
            cp16(sQh + doff, gqh + (size_t)r * HD + seg * 8);
            cp16(sQl + doff, gql + (size_t)r * HD + seg * 8);
        }
        #pragma unroll
        for (int j = 0; j < 2; j++) {
            int id  = tid + j * 256;          // 0..511
            int r   = id >> 3;                // 0..63
            int seg = id & 7;
            uint32_t doff = (uint32_t)(r * AQP + seg * 8) * 2;
            cp16(sKV + 0 * KT_ELEM * 2 + doff, gkh + (size_t)r * HD + seg * 8);
            cp16(sKV + 1 * KT_ELEM * 2 + doff, gkl + (size_t)r * HD + seg * 8);
            cp16(sKV + 2 * KT_ELEM * 2 + doff, gvh + (size_t)r * SS + seg * 8);
            cp16(sKV + 3 * KT_ELEM * 2 + doff, gvl + (size_t)r * SS + seg * 8);
        }
        CP_COMMIT();
    }

    float o_acc[8][4];
    #pragma unroll
    for (int nt = 0; nt < 8; nt++)
        #pragma unroll
        for (int e = 0; e < 4; e++) o_acc[nt][e] = 0.f;
    float m0v = -1e30f, m1v = -1e30f, l0v = 0.f, l1v = 0.f;

    const unsigned* mrow = g_mask + (size_t)bb * SS * (SS / 32);
    const int r0g = q0 + wq0 + g;
    const int r1g = r0g + 8;

    for (int kt = 0; kt < 16; kt++) {
        const int cur = kt & 1;
        if (kt + 1 < 16) {
            const int nxt = (kt + 1) & 1;
            const uint32_t base = sKV + (uint32_t)(nxt * 4 * KT_ELEM) * 2;
            const size_t koff = (size_t)(kt + 1) * 64;
            #pragma unroll
            for (int j = 0; j < 2; j++) {
                int id  = tid + j * 256;
                int r   = id >> 3;
                int seg = id & 7;
                uint32_t doff = (uint32_t)(r * AQP + seg * 8) * 2;
                cp16(base + 0 * KT_ELEM * 2 + doff, gkh + (koff + r) * HD + seg * 8);
                cp16(base + 1 * KT_ELEM * 2 + doff, gkl + (koff + r) * HD + seg * 8);
                cp16(base + 2 * KT_ELEM * 2 + doff, gvh + (size_t)r * SS + koff + seg * 8);
                cp16(base + 3 * KT_ELEM * 2 + doff, gvl + (size_t)r * SS + koff + seg * 8);
            }
            CP_COMMIT();
            asm volatile("cp.async.wait_group 1;" ::: "memory");
        } else {
            asm volatile("cp.async.wait_group 0;" ::: "memory");
        }
        __syncthreads();

        const __nv_bfloat16* Kh = KV + (cur * 4 + 0) * KT_ELEM;
        const __nv_bfloat16* Kl = KV + (cur * 4 + 1) * KT_ELEM;
        const __nv_bfloat16* Vh = KV + (cur * 4 + 2) * KT_ELEM;
        const __nv_bfloat16* Vl = KV + (cur * 4 + 3) * KT_ELEM;

        float sf[8][4];
        #pragma unroll
        for (int nt = 0; nt < 8; nt++)
            #pragma unroll
            for (int e = 0; e < 4; e++) sf[nt][e] = 0.f;

        #pragma unroll
        for (int kk = 0; kk < 4; kk++) {
            const int kb = kk * 16;
            uint32_t qah[4], qal[4];
            qah[0] = *(const uint32_t*)&Qh[(wq0 + g) * AQP + kb + 2 * t];
            qah[1] = *(const uint32_t*)&Qh[(wq0 + g + 8) * AQP + kb + 2 * t];
            qah[2] = *(const uint32_t*)&Qh[(wq0 + g) * AQP + kb + 2 * t + 8];
            qah[3] = *(const uint32_t*)&Qh[(wq0 + g + 8) * AQP + kb + 2 * t + 8];
            qal[0] = *(const uint32_t*)&Ql[(wq0 + g) * AQP + kb + 2 * t];
            qal[1] = *(const uint32_t*)&Ql[(wq0 + g + 8) * AQP + kb + 2 * t];
            qal[2] = *(const uint32_t*)&Ql[(wq0 + g) * AQP + kb + 2 * t + 8];
            qal[3] = *(const uint32_t*)&Ql[(wq0 + g + 8) * AQP + kb + 2 * t + 8];
            #pragma unroll
            for (int nt = 0; nt < 8; nt++) {
                uint32_t bh0 = *(const uint32_t*)&Kh[(nt * 8 + g) * AQP + kb + 2 * t];
                uint32_t bh1 = *(const uint32_t*)&Kh[(nt * 8 + g) * AQP + kb + 2 * t + 8];
                uint32_t bl0 = *(const uint32_t*)&Kl[(nt * 8 + g) * AQP + kb + 2 * t];
                uint32_t bl1 = *(const uint32_t*)&Kl[(nt * 8 + g) * AQP + kb + 2 * t + 8];
                float* d = sf[nt];
                mma16816(d[0], d[1], d[2], d[3], qah[0], qah[1], qah[2], qah[3], bh0, bh1);
                mma16816(d[0], d[1], d[2], d[3], qah[0], qah[1], qah[2], qah[3], bl0, bl1);
                mma16816(d[0], d[1], d[2], d[3], qal[0], qal[1], qal[2], qal[3], bh0, bh1);
            }
        }

        const unsigned w0 = mrow[(size_t)r0g * 32 + kt * 2];
        const unsigned w1 = mrow[(size_t)r0g * 32 + kt * 2 + 1];
        const unsigned w2 = mrow[(size_t)r1g * 32 + kt * 2];
        const unsigned w3 = mrow[(size_t)r1g * 32 + kt * 2 + 1];

        float mx0 = -1e30f, mx1 = -1e30f;
        #pragma unroll
        for (int nt = 0; nt < 8; nt++) {
            const unsigned wa = nt < 4 ? w0 : w1;
            const unsigned wb = nt < 4 ? w2 : w3;
            const int sh = (nt & 3) * 8 + 2 * t;
            float v0 = sf[nt][0] * 0.125f + (((wa >> sh) & 1u) ? 0.f : NEGV);
            float v1 = sf[nt][1] * 0.125f + (((wa >> (sh + 1)) & 1u) ? 0.f : NEGV);
            float v2 = sf[nt][2] * 0.125f + (((wb >> sh) & 1u) ? 0.f : NEGV);
            float v3 = sf[nt][3] * 0.125f + (((wb >> (sh + 1)) & 1u) ? 0.f : NEGV);
            sf[nt][0] = v0; sf[nt][1] = v1; sf[nt][2] = v2; sf[nt][3] = v3;
            mx0 = fmaxf(mx0, fmaxf(v0, v1));
            mx1 = fmaxf(mx1, fmaxf(v2, v3));
        }
        mx0 = fmaxf(mx0, __shfl_xor_sync(0xffffffffu, mx0, 1));
        mx0 = fmaxf(mx0, __shfl_xor_sync(0xffffffffu, mx0, 2));
        mx1 = fmaxf(mx1, __shfl_xor_sync(0xffffffffu, mx1, 1));
        mx1 = fmaxf(mx1, __shfl_xor_sync(0xffffffffu, mx1, 2));

        const float mn0 = fmaxf(m0v, mx0);
        const float mn1 = fmaxf(m1v, mx1);
        const float c0 = __expf(m0v - mn0);
        const float c1 = __expf(m1v - mn1);
        m0v = mn0; m1v = mn1;

        float sum0 = 0.f, sum1 = 0.f;
        uint32_t ph0[8], pl0[8], ph1[8], pl1[8];
        #pragma unroll
        for (int nt = 0; nt < 8; nt++) {
            float p00 = __expf(sf[nt][0] - mn0);
            float p01 = __expf(sf[nt][1] - mn0);
            float p10 = __expf(sf[nt][2] - mn1);
            float p11 = __expf(sf[nt][3] - mn1);
            sum0 += p00 + p01;
            sum1 += p10 + p11;
            __nv_bfloat162 hv0 = __floats2bfloat162_rn(p00, p01);
            __nv_bfloat162 lv0 = __floats2bfloat162_rn(
                p00 - __bfloat162float(hv0.x), p01 - __bfloat162float(hv0.y));
            __nv_bfloat162 hv1 = __floats2bfloat162_rn(p10, p11);
            __nv_bfloat162 lv1 = __floats2bfloat162_rn(
                p10 - __bfloat162float(hv1.x), p11 - __bfloat162float(hv1.y));
            ph0[nt] = *(uint32_t*)&hv0; pl0[nt] = *(uint32_t*)&lv0;
            ph1[nt] = *(uint32_t*)&hv1; pl1[nt] = *(uint32_t*)&lv1;
        }
        sum0 += __shfl_xor_sync(0xffffffffu, sum0, 1);
        sum0 += __shfl_xor_sync(0xffffffffu, sum0, 2);
        sum1 += __shfl_xor_sync(0xffffffffu, sum1, 1);
        sum1 += __shfl_xor_sync(0xffffffffu, sum1, 2);
        l0v = l0v * c0 + sum0;
        l1v = l1v * c1 + sum1;

        #pragma unroll
        for (int nt = 0; nt < 8; nt++) {
            o_acc[nt][0] *= c0; o_acc[nt][1] *= c0;
            o_acc[nt][2] *= c1; o_acc[nt][3] *= c1;
        }

        #pragma unroll
        for (int kc = 0; kc < 4; kc++) {
            const uint32_t ah0 = ph0[2 * kc],     ah1 = ph1[2 * kc];
            const uint32_t ah2 = ph0[2 * kc + 1], ah3 = ph1[2 * kc + 1];
            const uint32_t al0 = pl0[2 * kc],     al1 = pl1[2 * kc];
            const uint32_t al2 = pl0[2 * kc + 1], al3 = pl1[2 * kc + 1];
            #pragma unroll
            for (int nt = 0; nt < 8; nt++) {
                uint32_t bh0 = *(const uint32_t*)&Vh[(nt * 8 + g) * AQP + kc * 16 + 2 * t];
                uint32_t bh1 = *(const uint32_t*)&Vh[(nt * 8 + g) * AQP + kc * 16 + 2 * t + 8];
                uint32_t bl0 = *(const uint32_t*)&Vl[(nt * 8 + g) * AQP + kc * 16 + 2 * t];
                uint32_t bl1 = *(const uint32_t*)&Vl[(nt * 8 + g) * AQP + kc * 16 + 2 * t + 8];
                float* d = o_acc[nt];
                mma16816(d[0], d[1], d[2], d[3], ah0, ah1, ah2, ah3, bh0, bh1);
                mma16816(d[0], d[1], d[2], d[3], ah0, ah1, ah2, ah3, bl0, bl1);
                mma16816(d[0], d[1], d[2], d[3], al0, al1, al2, al3, bh0, bh1);
            }
        }
        __syncthreads();
    }

    const float inv0 = 1.f / l0v;
    const float inv1 = 1.f / l1v;
    #pragma unroll
    for (int nt = 0; nt < 8; nt++) {
        const int col = h * 64 + nt * 8 + 2 * t;
        float2 oa, ob;
        oa.x = fmaxf(o_acc[nt][0] * inv0, 0.f);
        oa.y = fmaxf(o_acc[nt][1] * inv0, 0.f);
        ob.x = fmaxf(o_acc[nt][2] * inv1, 0.f);
        ob.y = fmaxf(o_acc[nt][3] * inv1, 0.f);
        *(float2*)(out + ((size_t)bb * SS + r0g) * DD + col) = oa;
        *(float2*)(out + ((size_t)bb * SS + r1g) * DD + col) = ob;
    }
}

// ---------------------------------------------------------------------------
extern "C" void kernel_launch(void* const* d_in, const int* in_sizes, int n_in,
                              void* d_out, int out_size)
{
    const float* x   = (const float*)d_in[0];
    const float* adj = (const float*)d_in[1];
    const float* Wq  = (const float*)d_in[2];
    const float* bq  = (const float*)d_in[3];
    const float* Wk  = (const float*)d_in[4];
    const float* bk  = (const float*)d_in[5];
    const float* Wv  = (const float*)d_in[6];
    const float* bv  = (const float*)d_in[7];

    float* out     = (float*)d_out;
    float* out_adj = out + (size_t)BB * SS * DD;

    conv_x<<<(BB * SS * DD) / (256 * 4), 256>>>(x);
    conv_w<<<dim3(DD / 32, DD / 32, 3), dim3(32, 8)>>>(Wq, Wk, Wv);
    mask_pack<<<(BB * SS * (SS / 32)) / 256, 256>>>(adj, out_adj);

    cudaFuncSetAttribute(qkv_gemm_mma, cudaFuncAttributeMaxDynamicSharedMemorySize, GSMB);
    qkv_gemm_mma<<<dim3(DD / 128, (BB * SS) / 128, 3), 256, GSMB>>>(bq, bk, bv);
    v_conv<<<dim3(SS / 32, HD / 32, BB * HH), dim3(32, 8)>>>();

    const int attn_smem = (2 * QT_ELEM + 8 * KT_ELEM) * (int)sizeof(__nv_bfloat16);
    cudaFuncSetAttribute(attn_mma, cudaFuncAttributeMaxDynamicSharedMemorySize, attn_smem);
    attn_mma<<<dim3(SS / 128, HH, BB), 256, attn_smem>>>(out);
}

// round 11
// speedup vs baseline: 1.0211x; 1.0211x over previous
#include <cuda_runtime.h>
#include <cuda_bf16.h>
#include <cstdint>

#define BB 4
#define SS 1024
#define DD 1024
#define HH 16
#define HD 64
#define NEGV -10000000.0f

// ---------------------------------------------------------------------------
// Scratch (__device__ globals; no allocation allowed)
// ---------------------------------------------------------------------------
__device__ float g_v[BB*HH*SS*HD];                 // V fp32 (pre-transpose)
__device__ unsigned g_mask[BB*SS*(SS/32)];
__device__ __nv_bfloat16 g_xhi[BB*SS*DD];
__device__ __nv_bfloat16 g_xlo[BB*SS*DD];
__device__ __nv_bfloat16 g_whi[3][DD*DD];          // transposed: [n][k]
__device__ __nv_bfloat16 g_wlo[3][DD*DD];
__device__ __nv_bfloat16 g_qhi[BB*HH*SS*HD];       // [b,h,s,hd] (pre-scaled by 0.125)
__device__ __nv_bfloat16 g_qlo[BB*HH*SS*HD];
__device__ __nv_bfloat16 g_khi[BB*HH*SS*HD];       // [b,h,s,hd]
__device__ __nv_bfloat16 g_klo[BB*HH*SS*HD];
__device__ __nv_bfloat16 g_vthi[BB*HH*HD*SS];      // [b,h,hd,s]  (transposed)
__device__ __nv_bfloat16 g_vtlo[BB*HH*HD*SS];

// ---------------------------------------------------------------------------
// PTX helpers (baseline PTX only — works on plain sm_103 target)
// ---------------------------------------------------------------------------
__device__ __forceinline__ void mma16816(
    float& d0, float& d1, float& d2, float& d3,
    uint32_t a0, uint32_t a1, uint32_t a2, uint32_t a3,
    uint32_t b0, uint32_t b1)
{
    asm volatile(
        "mma.sync.aligned.m16n8k16.row.col.f32.bf16.bf16.f32 "
        "{%0,%1,%2,%3}, {%4,%5,%6,%7}, {%8,%9}, {%0,%1,%2,%3};"
        : "+f"(d0), "+f"(d1), "+f"(d2), "+f"(d3)
        : "r"(a0), "r"(a1), "r"(a2), "r"(a3), "r"(b0), "r"(b1));
}

__device__ __forceinline__ void ldm_x4(
    uint32_t& r0, uint32_t& r1, uint32_t& r2, uint32_t& r3, uint32_t addr)
{
    asm volatile("ldmatrix.sync.aligned.m8n8.x4.shared.b16 {%0,%1,%2,%3}, [%4];"
        : "=r"(r0), "=r"(r1), "=r"(r2), "=r"(r3) : "r"(addr));
}

__device__ __forceinline__ uint32_t smem_u32(const void* p) {
    uint32_t a;
    asm("{ .reg .u64 t; cvta.to.shared.u64 t, %1; cvt.u32.u64 %0, t; }"
        : "=r"(a) : "l"(p));
    return a;
}

__device__ __forceinline__ void cp16(uint32_t dst, const void* src) {
    asm volatile("cp.async.cg.shared.global [%0], [%1], 16;" :: "r"(dst), "l"(src));
}
#define CP_COMMIT() asm volatile("cp.async.commit_group;" ::: "memory")

// ---------------------------------------------------------------------------
// Prep: split x into bf16 hi/lo
// ---------------------------------------------------------------------------
__global__ __launch_bounds__(256) void conv_x(const float* __restrict__ x)
{
    size_t i = ((size_t)blockIdx.x * 256 + threadIdx.x) * 4;
    float4 v = *(const float4*)(x + i);
    __nv_bfloat16 h0 = __float2bfloat16(v.x);
    __nv_bfloat16 h1 = __float2bfloat16(v.y);
    __nv_bfloat16 h2 = __float2bfloat16(v.z);
    __nv_bfloat16 h3 = __float2bfloat16(v.w);
    __nv_bfloat16 l0 = __float2bfloat16(v.x - __bfloat162float(h0));
    __nv_bfloat16 l1 = __float2bfloat16(v.y - __bfloat162float(h1));
    __nv_bfloat16 l2 = __float2bfloat16(v.z - __bfloat162float(h2));
    __nv_bfloat16 l3 = __float2bfloat16(v.w - __bfloat162float(h3));
    __nv_bfloat162 p;
    p.x = h0; p.y = h1; *(__nv_bfloat162*)(g_xhi + i)     = p;
    p.x = h2; p.y = h3; *(__nv_bfloat162*)(g_xhi + i + 2) = p;
    p.x = l0; p.y = l1; *(__nv_bfloat162*)(g_xlo + i)     = p;
    p.x = l2; p.y = l3; *(__nv_bfloat162*)(g_xlo + i + 2) = p;
}

// ---------------------------------------------------------------------------
// Prep: transpose W [K,N] -> Wt [N,K], split hi/lo
// ---------------------------------------------------------------------------
__global__ __launch_bounds__(256) void conv_w(
    const float* __restrict__ Wq, const float* __restrict__ Wk, const float* __restrict__ Wv)
{
    const int z = blockIdx.z;
    const float* W = z == 0 ? Wq : (z == 1 ? Wk : Wv);
    __shared__ float t[32][33];
    int tx = threadIdx.x, ty = threadIdx.y;
    int n0 = blockIdx.x * 32, k0 = blockIdx.y * 32;
    #pragma unroll
    for (int r = 0; r < 4; r++) {
        int k = k0 + ty + r * 8;
        t[ty + r * 8][tx] = W[(size_t)k * DD + n0 + tx];
    }
    __syncthreads();
    #pragma unroll
    for (int r = 0; r < 4; r++) {
        int nn = n0 + ty + r * 8;
        int kk = k0 + tx;
        float v = t[tx][ty + r * 8];
        __nv_bfloat16 hi = __float2bfloat16(v);
        __nv_bfloat16 lo = __float2bfloat16(v - __bfloat162float(hi));
        g_whi[z][(size_t)nn * DD + kk] = hi;
        g_wlo[z][(size_t)nn * DD + kk] = lo;
    }
}

// ---------------------------------------------------------------------------
// QKV GEMM via mma.sync + 3-stage cp.async pipeline (single barrier/chunk).
// CTA 128x128, 8 warps (2Mx4N), warp tile 64x32, K-chunk 32.
// SMEM arrays: 128 rows x 32 bf16 (64 B/row), XOR-swizzled 16B chunks.
// 3 stages x 4 arrays x 8 KB = 96 KB  -> 2 CTAs/SM.
// ---------------------------------------------------------------------------
#define GT2   (128 * 32)
#define NSTG  3
#define GSMB  (NSTG * 4 * GT2 * 2)

__device__ __forceinline__ uint32_t gsw(int row, int chunk) {
    return (uint32_t)(row * 64 + ((chunk ^ ((row >> 1) & 3)) << 4));
}

__global__ __launch_bounds__(256, 2) void qkv_gemm_mma(
    const float* __restrict__ bq, const float* __restrict__ bk, const float* __restrict__ bv)
{
    extern __shared__ __nv_bfloat16 gsm[];

    const int tid  = threadIdx.x;
    const int lane = tid & 31;
    const int wid  = tid >> 5;
    const int wm   = wid >> 2;
    const int wn   = wid & 3;
    const int z    = blockIdx.z;
    const int m0   = blockIdx.y * 128;
    const int n0   = blockIdx.x * 128;

    const __nv_bfloat16* __restrict__ gAh = g_xhi;
    const __nv_bfloat16* __restrict__ gAl = g_xlo;
    const __nv_bfloat16* __restrict__ gBh = g_whi[z];
    const __nv_bfloat16* __restrict__ gBl = g_wlo[z];
    const float* bias = z == 0 ? bq : (z == 1 ? bk : bv);

    const uint32_t sb = smem_u32(gsm);

    float acc[4][4][4];
    #pragma unroll
    for (int mt = 0; mt < 4; mt++)
        #pragma unroll
        for (int nt = 0; nt < 4; nt++)
            #pragma unroll
            for (int r = 0; r < 4; r++) acc[mt][nt][r] = 0.f;

    const int fr = lane >> 2;
    const int fc = (lane & 3) * 2;

    auto issue_chunk = [&](int c) {
        const uint32_t base = sb + (uint32_t)((c % NSTG) * 4 * GT2) * 2;
        const int k0 = c * 32;
        #pragma unroll
        for (int i = 0; i < 2; i++) {
            const int idx = tid + i * 256;
            const int row = idx >> 2;
            const int seg = idx & 3;
            const uint32_t doff = gsw(row, seg);
            const size_t ao = (size_t)(m0 + row) * DD + k0 + seg * 8;
            const size_t bo = (size_t)(n0 + row) * DD + k0 + seg * 8;
            cp16(base + 0u * GT2 * 2 + doff, gAh + ao);
            cp16(base + 1u * GT2 * 2 + doff, gAl + ao);
            cp16(base + 2u * GT2 * 2 + doff, gBh + bo);
            cp16(base + 3u * GT2 * 2 + doff, gBl + bo);
        }
        CP_COMMIT();
    };

    issue_chunk(0);
    issue_chunk(1);

    for (int c = 0; c < 32; c++) {
        if (c < 30) asm volatile("cp.async.wait_group 1;" ::: "memory");
        else        asm volatile("cp.async.wait_group 0;" ::: "memory");
        __syncthreads();

        const uint32_t sbase = sb + (uint32_t)((c % NSTG) * 4 * GT2) * 2;
        #pragma unroll
        for (int ks = 0; ks < 2; ks++) {
            const int kc = ks * 2;
            uint32_t ah[4][4], al[4][4], bh[4][2], bl[4][2];
            #pragma unroll
            for (int mt = 0; mt < 4; mt++) {
                const int row = wm * 64 + mt * 16 + (lane & 15);
                const uint32_t aoff = gsw(row, kc + (lane >> 4));
                ldm_x4(ah[mt][0], ah[mt][1], ah[mt][2], ah[mt][3],
                       sbase + 0u * GT2 * 2 + aoff);
                ldm_x4(al[mt][0], al[mt][1], al[mt][2], al[mt][3],
                       sbase + 1u * GT2 * 2 + aoff);
            }
            #pragma unroll
            for (int np = 0; np < 2; np++) {
                const int row = wn * 32 + np * 16 + (lane & 7) + ((lane >> 4) << 3);
                const uint32_t boff = gsw(row, kc + ((lane >> 3) & 1));
                ldm_x4(bh[np * 2][0], bh[np * 2][1], bh[np * 2 + 1][0], bh[np * 2 + 1][1],
                       sbase + 2u * GT2 * 2 + boff);
                ldm_x4(bl[np * 2][0], bl[np * 2][1], bl[np * 2 + 1][0], bl[np * 2 + 1][1],
                       sbase + 3u * GT2 * 2 + boff);
            }
            #pragma unroll
            for (int mt = 0; mt < 4; mt++)
                #pragma unroll
                for (int nt = 0; nt < 4; nt++)
                    mma16816(acc[mt][nt][0], acc[mt][nt][1], acc[mt][nt][2], acc[mt][nt][3],
                             ah[mt][0], ah[mt][1], ah[mt][2], ah[mt][3],
                             bh[nt][0], bh[nt][1]);
            #pragma unroll
            for (int mt = 0; mt < 4; mt++)
                #pragma unroll
                for (int nt = 0; nt < 4; nt++)
                    mma16816(acc[mt][nt][0], acc[mt][nt][1], acc[mt][nt][2], acc[mt][nt][3],
                             ah[mt][0], ah[mt][1], ah[mt][2], ah[mt][3],
                             bl[nt][0], bl[nt][1]);
            #pragma unroll
            for (int mt = 0; mt < 4; mt++)
                #pragma unroll
                for (int nt = 0; nt < 4; nt++)
                    mma16816(acc[mt][nt][0], acc[mt][nt][1], acc[mt][nt][2], acc[mt][nt][3],
                             al[mt][0], al[mt][1], al[mt][2], al[mt][3],
                             bh[nt][0], bh[nt][1]);
        }

        if (c + 2 < 32) issue_chunk(c + 2);
    }

    __nv_bfloat16* ohi = z == 0 ? g_qhi : g_khi;
    __nv_bfloat16* olo = z == 0 ? g_qlo : g_klo;
    const float sc = (z == 0) ? 0.125f : 1.0f;   // fold 1/sqrt(HD) into Q

    #pragma unroll
    for (int nt = 0; nt < 4; nt++) {
        const int n = n0 + wn * 32 + nt * 8 + fc;
        const int h = n >> 6;
        const int hd = n & 63;
        const float bv0 = bias[n];
        const float bv1 = bias[n + 1];
        #pragma unroll
        for (int mt = 0; mt < 4; mt++) {
            #pragma unroll
            for (int half = 0; half < 2; half++) {
                const int m = m0 + wm * 64 + mt * 16 + fr + half * 8;
                const int bb = m >> 10;
                const int s = m & 1023;
                float v0 = (acc[mt][nt][half * 2 + 0] + bv0) * sc;
                float v1 = (acc[mt][nt][half * 2 + 1] + bv1) * sc;
                size_t idx = ((size_t)(bb * HH + h) * SS + s) * HD + hd;
                if (z < 2) {
                    __nv_bfloat162 hv = __floats2bfloat162_rn(v0, v1);
                    __nv_bfloat162 lv = __floats2bfloat162_rn(
                        v0 - __bfloat162float(hv.x), v1 - __bfloat162float(hv.y));
                    *(__nv_bfloat162*)(ohi + idx) = hv;
                    *(__nv_bfloat162*)(olo + idx) = lv;
                } else {
                    float2 o; o.x = v0; o.y = v1;
                    *(float2*)(g_v + idx) = o;
                }
            }
        }
    }
}

// ---------------------------------------------------------------------------
// V: transpose [b,h,s,hd] f32 -> [b,h,hd,s] bf16 hi/lo
// ---------------------------------------------------------------------------
__global__ __launch_bounds__(256) void v_conv()
{
    __shared__ float t[32][33];
    const int bh = blockIdx.z;
    const int s0 = blockIdx.x * 32;
    const int hd0 = blockIdx.y * 32;
    const int tx = threadIdx.x, ty = threadIdx.y;
    #pragma unroll
    for (int r = 0; r < 4; r++) {
        int s = s0 + ty + r * 8;
        t[ty + r * 8][tx] = g_v[((size_t)bh * SS + s) * HD + hd0 + tx];
    }
    __syncthreads();
    #pragma unroll
    for (int r = 0; r < 4; r++) {
        int hd = hd0 + ty + r * 8;
        int s = s0 + tx;
        float v = t[tx][ty + r * 8];
        __nv_bfloat16 hi = __float2bfloat16(v);
        __nv_bfloat16 lo = __float2bfloat16(v - __bfloat162float(hi));
        g_vthi[((size_t)bh * HD + hd) * SS + s] = hi;
        g_vtlo[((size_t)bh * HD + hd) * SS + s] = lo;
    }
}

// ---------------------------------------------------------------------------
// Pack adj into 1-bit mask and copy adj to second output region.
// ---------------------------------------------------------------------------
__global__ __launch_bounds__(256) void mask_pack(
    const float* __restrict__ adj, float* __restrict__ adj_out)
{
    int w = blockIdx.x * blockDim.x + threadIdx.x;
    const float4* a4 = (const float4*)adj;
    float4* o4 = (float4*)adj_out;
    unsigned bits = 0;
    #pragma unroll
    for (int i = 0; i < 8; i++) {
        float4 v = a4[(size_t)w * 8 + i];
        o4[(size_t)w * 8 + i] = v;
        bits |= (v.x >= 0.5f ? 1u : 0u) << (i * 4 + 0);
        bits |= (v.y >= 0.5f ? 1u : 0u) << (i * 4 + 1);
        bits |= (v.z >= 0.5f ? 1u : 0u) << (i * 4 + 2);
        bits |= (v.w >= 0.5f ? 1u : 0u) << (i * 4 + 3);
    }
    g_mask[w] = bits;
}

// ---------------------------------------------------------------------------
// Flash attention via mma.sync: q-tile 128, 256 threads (8 warps x 16 rows),
// K/V tiles 64 double-buffered with cp.async; ldmatrix fragment loads.
// Row stride AQP=72 elem (144 B, odd multiple of 16 B) -> conflict-free.
// ---------------------------------------------------------------------------
#define AQP 72
#define KT_ELEM (64 * AQP)            // K/V tile array (64 rows)
#define QT_ELEM (128 * AQP)           // Q tile array (128 rows)

__global__ __launch_bounds__(256, 2) void attn_mma(float* __restrict__ out)
{
    extern __shared__ __nv_bfloat16 smp[];
    __nv_bfloat16* Qh = smp;                      // [128][AQP]
    __nv_bfloat16* Ql = Qh + QT_ELEM;
    __nv_bfloat16* KV = Ql + QT_ELEM;             // 2 stages x {Kh,Kl,Vh,Vl}

    const int tid  = threadIdx.x;
    const int lane = tid & 31;
    const int warp = tid >> 5;
    const int g    = lane >> 2;
    const int t    = lane & 3;
    const int q0   = blockIdx.x * 128;
    const int h    = blockIdx.y;
    const int bb   = blockIdx.z;
    const int wq0  = warp * 16;

    const size_t bhs = ((size_t)(bb * HH + h)) * SS;
    const __nv_bfloat16* gqh = g_qhi + (bhs + q0) * HD;
    const __nv_bfloat16* gql = g_qlo + (bhs + q0) * HD;
    const __nv_bfloat16* gkh = g_khi + bhs * HD;
    const __nv_bfloat16* gkl = g_klo + bhs * HD;
    const __nv_bfloat16* gvh = g_vthi + ((size_t)(bb * HH + h)) * HD * SS;
    const __nv_bfloat16* gvl = g_vtlo + ((size_t)(bb * HH + h)) * HD * SS;

    const uint32_t sQh = smem_u32(Qh);
    const uint32_t sQl = smem_u32(Ql);
    const uint32_t sKV = smem_u32(KV);

    // ---- issue Q (128 rows) + K/V tile 0 ----
    {
        #pragma unroll
        for (int j = 0; j < 4; j++) {
            int id  = tid + j * 256;          // 0..1023
            int r   = id >> 3;                // 0..127
            int seg = id & 7;
            uint32_t doff = (uint32_t)(r * AQP + seg * 8) * 2;
            cp16(sQh + doff, gqh + (size_t)r * HD + seg * 8);
            cp16(sQl + doff, gql + (size_t)r * HD + seg * 8);
        }
        #pragma unroll
        for (int j = 0; j < 2; j++) {
            int id  = tid + j * 256;          // 0..511
            int r   = id >> 3;                // 0..63
            int seg = id & 7;
            uint32_t doff = (uint32_t)(r * AQP + seg * 8) * 2;
            cp16(sKV + 0 * KT_ELEM * 2 + doff, gkh + (size_t)r * HD + seg * 8);
            cp16(sKV + 1 * KT_ELEM * 2 + doff, gkl + (size_t)r * HD + seg * 8);
            cp16(sKV + 2 * KT_ELEM * 2 + doff, gvh + (size_t)r * SS + seg * 8);
            cp16(sKV + 3 * KT_ELEM * 2 + doff, gvl + (size_t)r * SS + seg * 8);
        }
        CP_COMMIT();
    }

    float o_acc[8][4];
    #pragma unroll
    for (int nt = 0; nt < 8; nt++)
        #pragma unroll
        for (int e = 0; e < 4; e++) o_acc[nt][e] = 0.f;
    float m0v = -1e30f, m1v = -1e30f, l0v = 0.f, l1v = 0.f;

    const unsigned* mrow = g_mask + (size_t)bb * SS * (SS / 32);
    const int r0g = q0 + wq0 + g;
    const int r1g = r0g + 8;

    // ldmatrix lane-address components (A-pattern for Q, B-pattern for K/V)
    const uint32_t a_row  = (uint32_t)(wq0 + (lane & 15));
    const uint32_t a_cofs = (uint32_t)((lane >> 4) << 3);
    const uint32_t b_rofs = (uint32_t)((lane & 7) + ((lane >> 4) << 3));
    const uint32_t b_cofs = (uint32_t)(((lane >> 3) & 1) << 3);

    for (int kt = 0; kt < 16; kt++) {
        const int cur = kt & 1;
        if (kt + 1 < 16) {
            const int nxt = (kt + 1) & 1;
            const uint32_t base = sKV + (uint32_t)(nxt * 4 * KT_ELEM) * 2;
            const size_t koff = (size_t)(kt + 1) * 64;
            #pragma unroll
            for (int j = 0; j < 2; j++) {
                int id  = tid + j * 256;
                int r   = id >> 3;
                int seg = id & 7;
                uint32_t doff = (uint32_t)(r * AQP + seg * 8) * 2;
                cp16(base + 0 * KT_ELEM * 2 + doff, gkh + (koff + r) * HD + seg * 8);
                cp16(base + 1 * KT_ELEM * 2 + doff, gkl + (koff + r) * HD + seg * 8);
                cp16(base + 2 * KT_ELEM * 2 + doff, gvh + (size_t)r * SS + koff + seg * 8);
                cp16(base + 3 * KT_ELEM * 2 + doff, gvl + (size_t)r * SS + koff + seg * 8);
            }
            CP_COMMIT();
            asm volatile("cp.async.wait_group 1;" ::: "memory");
        } else {
            asm volatile("cp.async.wait_group 0;" ::: "memory");
        }
        __syncthreads();

        const uint32_t sKh = sKV + (uint32_t)((cur * 4 + 0) * KT_ELEM) * 2;
        const uint32_t sKl = sKV + (uint32_t)((cur * 4 + 1) * KT_ELEM) * 2;
        const uint32_t sVh = sKV + (uint32_t)((cur * 4 + 2) * KT_ELEM) * 2;
        const uint32_t sVl = sKV + (uint32_t)((cur * 4 + 3) * KT_ELEM) * 2;

        // ---- S = Q K^T (3-term split), ldmatrix fragments ----
        float sf[8][4];
        #pragma unroll
        for (int nt = 0; nt < 8; nt++)
            #pragma unroll
            for (int e = 0; e < 4; e++) sf[nt][e] = 0.f;

        #pragma unroll
        for (int kk = 0; kk < 4; kk++) {
            const uint32_t kb = kk * 16;
            uint32_t qah[4], qal[4];
            const uint32_t aoff = (a_row * AQP + kb + a_cofs) * 2;
            ldm_x4(qah[0], qah[1], qah[2], qah[3], sQh + aoff);
            ldm_x4(qal[0], qal[1], qal[2], qal[3], sQl + aoff);
            #pragma unroll
            for (int np = 0; np < 4; np++) {
                uint32_t kh0, kh1, kh2, kh3, kl0, kl1, kl2, kl3;
                const uint32_t boff = ((np * 16 + b_rofs) * AQP + kb + b_cofs) * 2;
                ldm_x4(kh0, kh1, kh2, kh3, sKh + boff);
                ldm_x4(kl0, kl1, kl2, kl3, sKl + boff);
                float* d0 = sf[np * 2];
                float* d1 = sf[np * 2 + 1];
                mma16816(d0[0], d0[1], d0[2], d0[3], qah[0], qah[1], qah[2], qah[3], kh0, kh1);
                mma16816(d1[0], d1[1], d1[2], d1[3], qah[0], qah[1], qah[2], qah[3], kh2, kh3);
                mma16816(d0[0], d0[1], d0[2], d0[3], qah[0], qah[1], qah[2], qah[3], kl0, kl1);
                mma16816(d1[0], d1[1], d1[2], d1[3], qah[0], qah[1], qah[2], qah[3], kl2, kl3);
                mma16816(d0[0], d0[1], d0[2], d0[3], qal[0], qal[1], qal[2], qal[3], kh0, kh1);
                mma16816(d1[0], d1[1], d1[2], d1[3], qal[0], qal[1], qal[2], qal[3], kh2, kh3);
            }
        }

        // ---- mask + online softmax (Q pre-scaled by 0.125 in GEMM) ----
        const unsigned w0 = mrow[(size_t)r0g * 32 + kt * 2];
        const unsigned w1 = mrow[(size_t)r0g * 32 + kt * 2 + 1];
        const unsigned w2 = mrow[(size_t)r1g * 32 + kt * 2];
        const unsigned w3 = mrow[(size_t)r1g * 32 + kt * 2 + 1];

        float mx0 = -1e30f, mx1 = -1e30f;
        #pragma unroll
        for (int nt = 0; nt < 8; nt++) {
            const unsigned wa = nt < 4 ? w0 : w1;
            const unsigned wb = nt < 4 ? w2 : w3;
            const int sh = (nt & 3) * 8 + 2 * t;
            float v0 = sf[nt][0] + (((wa >> sh) & 1u) ? 0.f : NEGV);
            float v1 = sf[nt][1] + (((wa >> (sh + 1)) & 1u) ? 0.f : NEGV);
            float v2 = sf[nt][2] + (((wb >> sh) & 1u) ? 0.f : NEGV);
            float v3 = sf[nt][3] + (((wb >> (sh + 1)) & 1u) ? 0.f : NEGV);
            sf[nt][0] = v0; sf[nt][1] = v1; sf[nt][2] = v2; sf[nt][3] = v3;
            mx0 = fmaxf(mx0, fmaxf(v0, v1));
            mx1 = fmaxf(mx1, fmaxf(v2, v3));
        }
        mx0 = fmaxf(mx0, __shfl_xor_sync(0xffffffffu, mx0, 1));
        mx0 = fmaxf(mx0, __shfl_xor_sync(0xffffffffu, mx0, 2));
        mx1 = fmaxf(mx1, __shfl_xor_sync(0xffffffffu, mx1, 1));
        mx1 = fmaxf(mx1, __shfl_xor_sync(0xffffffffu, mx1, 2));

        const float mn0 = fmaxf(m0v, mx0);
        const float mn1 = fmaxf(m1v, mx1);
        const float c0 = __expf(m0v - mn0);
        const float c1 = __expf(m1v - mn1);
        m0v = mn0; m1v = mn1;

        float sum0 = 0.f, sum1 = 0.f;
        uint32_t ph0[8], pl0[8], ph1[8], pl1[8];
        #pragma unroll
        for (int nt = 0; nt < 8; nt++) {
            float p00 = __expf(sf[nt][0] - mn0);
            float p01 = __expf(sf[nt][1] - mn0);
            float p10 = __expf(sf[nt][2] - mn1);
            float p11 = __expf(sf[nt][3] - mn1);
            sum0 += p00 + p01;
            sum1 += p10 + p11;
            __nv_bfloat162 hv0 = __floats2bfloat162_rn(p00, p01);
            __nv_bfloat162 lv0 = __floats2bfloat162_rn(
                p00 - __bfloat162float(hv0.x), p01 - __bfloat162float(hv0.y));
            __nv_bfloat162 hv1 = __floats2bfloat162_rn(p10, p11);
            __nv_bfloat162 lv1 = __floats2bfloat162_rn(
                p10 - __bfloat162float(hv1.x), p11 - __bfloat162float(hv1.y));
            ph0[nt] = *(uint32_t*)&hv0; pl0[nt] = *(uint32_t*)&lv0;
            ph1[nt] = *(uint32_t*)&hv1; pl1[nt] = *(uint32_t*)&lv1;
        }
        sum0 += __shfl_xor_sync(0xffffffffu, sum0, 1);
        sum0 += __shfl_xor_sync(0xffffffffu, sum0, 2);
        sum1 += __shfl_xor_sync(0xffffffffu, sum1, 1);
        sum1 += __shfl_xor_sync(0xffffffffu, sum1, 2);
        l0v = l0v * c0 + sum0;
        l1v = l1v * c1 + sum1;

        #pragma unroll
        for (int nt = 0; nt < 8; nt++) {
            o_acc[nt][0] *= c0; o_acc[nt][1] *= c0;
            o_acc[nt][2] *= c1; o_acc[nt][3] *= c1;
        }

        // ---- O += P V (3-term split), ldmatrix V fragments ----
        #pragma unroll
        for (int kc = 0; kc < 4; kc++) {
            const uint32_t ah0 = ph0[2 * kc],     ah1 = ph1[2 * kc];
            const uint32_t ah2 = ph0[2 * kc + 1], ah3 = ph1[2 * kc + 1];
            const uint32_t al0 = pl0[2 * kc],     al1 = pl1[2 * kc];
            const uint32_t al2 = pl0[2 * kc + 1], al3 = pl1[2 * kc + 1];
            #pragma unroll
            for (int np = 0; np < 4; np++) {
                uint32_t vh0, vh1, vh2, vh3, vl0, vl1, vl2, vl3;
                const uint32_t boff = ((np * 16 + b_rofs) * AQP + kc * 16 + b_cofs) * 2;
                ldm_x4(vh0, vh1, vh2, vh3, sVh + boff);
                ldm_x4(vl0, vl1, vl2, vl3, sVl + boff);
                float* d0 = o_acc[np * 2];
                float* d1 = o_acc[np * 2 + 1];
                mma16816(d0[0], d0[1], d0[2], d0[3], ah0, ah1, ah2, ah3, vh0, vh1);
                mma16816(d1[0], d1[1], d1[2], d1[3], ah0, ah1, ah2, ah3, vh2, vh3);
                mma16816(d0[0], d0[1], d0[2], d0[3], ah0, ah1, ah2, ah3, vl0, vl1);
                mma16816(d1[0], d1[1], d1[2], d1[3], ah0, ah1, ah2, ah3, vl2, vl3);
                mma16816(d0[0], d0[1], d0[2], d0[3], al0, al1, al2, al3, vh0, vh1);
                mma16816(d1[0], d1[1], d1[2], d1[3], al0, al1, al2, al3, vh2, vh3);
            }
        }
        __syncthreads();
    }

    const float inv0 = 1.f / l0v;
    const float inv1 = 1.f / l1v;
    #pragma unroll
    for (int nt = 0; nt < 8; nt++) {
        const int col = h * 64 + nt * 8 + 2 * t;
        float2 oa, ob;
        oa.x = fmaxf(o_acc[nt][0] * inv0, 0.f);
        oa.y = fmaxf(o_acc[nt][1] * inv0, 0.f);
        ob.x = fmaxf(o_acc[nt][2] * inv1, 0.f);
        ob.y = fmaxf(o_acc[nt][3] * inv1, 0.f);
        *(float2*)(out + ((size_t)bb * SS + r0g) * DD + col) = oa;
        *(float2*)(out + ((size_t)bb * SS + r1g) * DD + col) = ob;
    }
}

// ---------------------------------------------------------------------------
extern "C" void kernel_launch(void* const* d_in, const int* in_sizes, int n_in,
                              void* d_out, int out_size)
{
    const float* x   = (const float*)d_in[0];
    const float* adj = (const float*)d_in[1];
    const float* Wq  = (const float*)d_in[2];
    const float* bq  = (const float*)d_in[3];
    const float* Wk  = (const float*)d_in[4];
    const float* bk  = (const float*)d_in[5];
    const float* Wv  = (const float*)d_in[6];
    const float* bv  = (const float*)d_in[7];

    float* out     = (float*)d_out;
    float* out_adj = out + (size_t)BB * SS * DD;

    conv_x<<<(BB * SS * DD) / (256 * 4), 256>>>(x);
    conv_w<<<dim3(DD / 32, DD / 32, 3), dim3(32, 8)>>>(Wq, Wk, Wv);
    mask_pack<<<(BB * SS * (SS / 32)) / 256, 256>>>(adj, out_adj);

    cudaFuncSetAttribute(qkv_gemm_mma, cudaFuncAttributeMaxDynamicSharedMemorySize, GSMB);
    qkv_gemm_mma<<<dim3(DD / 128, (BB * SS) / 128, 3), 256, GSMB>>>(bq, bk, bv);
    v_conv<<<dim3(SS / 32, HD / 32, BB * HH), dim3(32, 8)>>>();

    const int attn_smem = (2 * QT_ELEM + 8 * KT_ELEM) * (int)sizeof(__nv_bfloat16);
    cudaFuncSetAttribute(attn_mma, cudaFuncAttributeMaxDynamicSharedMemorySize, attn_smem);
    attn_mma<<<dim3(SS / 128, HH, BB), 256, attn_smem>>>(out);
}

// round 12
// speedup vs baseline: 1.0617x; 1.0397x over previous
#include <cuda_runtime.h>
#include <cuda_bf16.h>
#include <cstdint>

#define BB 4
#define SS 1024
#define DD 1024
#define HH 16
#define HD 64
#define NEGV -10000000.0f
#define SCQ 0.18033688011112042f   /* 0.125 * log2(e) */

// ---------------------------------------------------------------------------
// Scratch (__device__ globals; no allocation allowed)
// ---------------------------------------------------------------------------
__device__ unsigned g_mask[BB*SS*(SS/32)];
__device__ __nv_bfloat16 g_xhi[BB*SS*DD];
__device__ __nv_bfloat16 g_xlo[BB*SS*DD];
__device__ __nv_bfloat16 g_whi[3][DD*DD];          // transposed: [n][k]
__device__ __nv_bfloat16 g_wlo[3][DD*DD];
__device__ __nv_bfloat16 g_qhi[BB*HH*SS*HD];       // [b,h,s,hd] (pre-scaled by SCQ)
__device__ __nv_bfloat16 g_qlo[BB*HH*SS*HD];
__device__ __nv_bfloat16 g_khi[BB*HH*SS*HD];       // [b,h,s,hd]
__device__ __nv_bfloat16 g_klo[BB*HH*SS*HD];
__device__ __nv_bfloat16 g_vthi[BB*HH*HD*SS];      // [b,h,hd,s]  (transposed)
__device__ __nv_bfloat16 g_vtlo[BB*HH*HD*SS];

// ---------------------------------------------------------------------------
// PTX helpers (baseline PTX only — works on plain sm_103 target)
// ---------------------------------------------------------------------------
__device__ __forceinline__ void mma16816(
    float& d0, float& d1, float& d2, float& d3,
    uint32_t a0, uint32_t a1, uint32_t a2, uint32_t a3,
    uint32_t b0, uint32_t b1)
{
    asm volatile(
        "mma.sync.aligned.m16n8k16.row.col.f32.bf16.bf16.f32 "
        "{%0,%1,%2,%3}, {%4,%5,%6,%7}, {%8,%9}, {%0,%1,%2,%3};"
        : "+f"(d0), "+f"(d1), "+f"(d2), "+f"(d3)
        : "r"(a0), "r"(a1), "r"(a2), "r"(a3), "r"(b0), "r"(b1));
}

__device__ __forceinline__ void ldm_x4(
    uint32_t& r0, uint32_t& r1, uint32_t& r2, uint32_t& r3, uint32_t addr)
{
    asm volatile("ldmatrix.sync.aligned.m8n8.x4.shared.b16 {%0,%1,%2,%3}, [%4];"
        : "=r"(r0), "=r"(r1), "=r"(r2), "=r"(r3) : "r"(addr));
}

__device__ __forceinline__ uint32_t smem_u32(const void* p) {
    uint32_t a;
    asm("{ .reg .u64 t; cvta.to.shared.u64 t, %1; cvt.u32.u64 %0, t; }"
        : "=r"(a) : "l"(p));
    return a;
}

__device__ __forceinline__ void cp16(uint32_t dst, const void* src) {
    asm volatile("cp.async.cg.shared.global [%0], [%1], 16;" :: "r"(dst), "l"(src));
}
#define CP_COMMIT() asm volatile("cp.async.commit_group;" ::: "memory")

// ---------------------------------------------------------------------------
// Prep: split x into bf16 hi/lo
// ---------------------------------------------------------------------------
__global__ __launch_bounds__(256) void conv_x(const float* __restrict__ x)
{
    size_t i = ((size_t)blockIdx.x * 256 + threadIdx.x) * 4;
    float4 v = *(const float4*)(x + i);
    __nv_bfloat16 h0 = __float2bfloat16(v.x);
    __nv_bfloat16 h1 = __float2bfloat16(v.y);
    __nv_bfloat16 h2 = __float2bfloat16(v.z);
    __nv_bfloat16 h3 = __float2bfloat16(v.w);
    __nv_bfloat16 l0 = __float2bfloat16(v.x - __bfloat162float(h0));
    __nv_bfloat16 l1 = __float2bfloat16(v.y - __bfloat162float(h1));
    __nv_bfloat16 l2 = __float2bfloat16(v.z - __bfloat162float(h2));
    __nv_bfloat16 l3 = __float2bfloat16(v.w - __bfloat162float(h3));
    __nv_bfloat162 p;
    p.x = h0; p.y = h1; *(__nv_bfloat162*)(g_xhi + i)     = p;
    p.x = h2; p.y = h3; *(__nv_bfloat162*)(g_xhi + i + 2) = p;
    p.x = l0; p.y = l1; *(__nv_bfloat162*)(g_xlo + i)     = p;
    p.x = l2; p.y = l3; *(__nv_bfloat162*)(g_xlo + i + 2) = p;
}

// ---------------------------------------------------------------------------
// Prep: transpose W [K,N] -> Wt [N,K], split hi/lo
// ---------------------------------------------------------------------------
__global__ __launch_bounds__(256) void conv_w(
    const float* __restrict__ Wq, const float* __restrict__ Wk, const float* __restrict__ Wv)
{
    const int z = blockIdx.z;
    const float* W = z == 0 ? Wq : (z == 1 ? Wk : Wv);
    __shared__ float t[32][33];
    int tx = threadIdx.x, ty = threadIdx.y;
    int n0 = blockIdx.x * 32, k0 = blockIdx.y * 32;
    #pragma unroll
    for (int r = 0; r < 4; r++) {
        int k = k0 + ty + r * 8;
        t[ty + r * 8][tx] = W[(size_t)k * DD + n0 + tx];
    }
    __syncthreads();
    #pragma unroll
    for (int r = 0; r < 4; r++) {
        int nn = n0 + ty + r * 8;
        int kk = k0 + tx;
        float v = t[tx][ty + r * 8];
        __nv_bfloat16 hi = __float2bfloat16(v);
        __nv_bfloat16 lo = __float2bfloat16(v - __bfloat162float(hi));
        g_whi[z][(size_t)nn * DD + kk] = hi;
        g_wlo[z][(size_t)nn * DD + kk] = lo;
    }
}

// ---------------------------------------------------------------------------
// QKV GEMM via mma.sync + 3-stage cp.async pipeline (single barrier/chunk).
// Q epilogue pre-scales by SCQ; V epilogue writes transposed bf16 hi/lo.
// ---------------------------------------------------------------------------
#define GT2   (128 * 32)
#define NSTG  3
#define GSMB  (NSTG * 4 * GT2 * 2)

__device__ __forceinline__ uint32_t gsw(int row, int chunk) {
    return (uint32_t)(row * 64 + ((chunk ^ ((row >> 1) & 3)) << 4));
}

__global__ __launch_bounds__(256, 2) void qkv_gemm_mma(
    const float* __restrict__ bq, const float* __restrict__ bk, const float* __restrict__ bv)
{
    extern __shared__ __nv_bfloat16 gsm[];

    const int tid  = threadIdx.x;
    const int lane = tid & 31;
    const int wid  = tid >> 5;
    const int wm   = wid >> 2;
    const int wn   = wid & 3;
    const int z    = blockIdx.z;
    const int m0   = blockIdx.y * 128;
    const int n0   = blockIdx.x * 128;

    const __nv_bfloat16* __restrict__ gAh = g_xhi;
    const __nv_bfloat16* __restrict__ gAl = g_xlo;
    const __nv_bfloat16* __restrict__ gBh = g_whi[z];
    const __nv_bfloat16* __restrict__ gBl = g_wlo[z];
    const float* bias = z == 0 ? bq : (z == 1 ? bk : bv);

    const uint32_t sb = smem_u32(gsm);

    float acc[4][4][4];
    #pragma unroll
    for (int mt = 0; mt < 4; mt++)
        #pragma unroll
        for (int nt = 0; nt < 4; nt++)
            #pragma unroll
            for (int r = 0; r < 4; r++) acc[mt][nt][r] = 0.f;

    const int fr = lane >> 2;
    const int fc = (lane & 3) * 2;

    auto issue_chunk = [&](int c) {
        const uint32_t base = sb + (uint32_t)((c % NSTG) * 4 * GT2) * 2;
        const int k0 = c * 32;
        #pragma unroll
        for (int i = 0; i < 2; i++) {
            const int idx = tid + i * 256;
            const int row = idx >> 2;
            const int seg = idx & 3;
            const uint32_t doff = gsw(row, seg);
            const size_t ao = (size_t)(m0 + row) * DD + k0 + seg * 8;
            const size_t bo = (size_t)(n0 + row) * DD + k0 + seg * 8;
            cp16(base + 0u * GT2 * 2 + doff, gAh + ao);
            cp16(base + 1u * GT2 * 2 + doff, gAl + ao);
            cp16(base + 2u * GT2 * 2 + doff, gBh + bo);
            cp16(base + 3u * GT2 * 2 + doff, gBl + bo);
        }
        CP_COMMIT();
    };

    issue_chunk(0);
    issue_chunk(1);

    for (int c = 0; c < 32; c++) {
        if (c < 30) asm volatile("cp.async.wait_group 1;" ::: "memory");
        else        asm volatile("cp.async.wait_group 0;" ::: "memory");
        __syncthreads();

        const uint32_t sbase = sb + (uint32_t)((c % NSTG) * 4 * GT2) * 2;
        #pragma unroll
        for (int ks = 0; ks < 2; ks++) {
            const int kc = ks * 2;
            uint32_t ah[4][4], al[4][4], bh[4][2], bl[4][2];
            #pragma unroll
            for (int mt = 0; mt < 4; mt++) {
                const int row = wm * 64 + mt * 16 + (lane & 15);
                const uint32_t aoff = gsw(row, kc + (lane >> 4));
                ldm_x4(ah[mt][0], ah[mt][1], ah[mt][2], ah[mt][3],
                       sbase + 0u * GT2 * 2 + aoff);
                ldm_x4(al[mt][0], al[mt][1], al[mt][2], al[mt][3],
                       sbase + 1u * GT2 * 2 + aoff);
            }
            #pragma unroll
            for (int np = 0; np < 2; np++) {
                const int row = wn * 32 + np * 16 + (lane & 7) + ((lane >> 4) << 3);
                const uint32_t boff = gsw(row, kc + ((lane >> 3) & 1));
                ldm_x4(bh[np * 2][0], bh[np * 2][1], bh[np * 2 + 1][0], bh[np * 2 + 1][1],
                       sbase + 2u * GT2 * 2 + boff);
                ldm_x4(bl[np * 2][0], bl[np * 2][1], bl[np * 2 + 1][0], bl[np * 2 + 1][1],
                       sbase + 3u * GT2 * 2 + boff);
            }
            #pragma unroll
            for (int mt = 0; mt < 4; mt++)
                #pragma unroll
                for (int nt = 0; nt < 4; nt++)
                    mma16816(acc[mt][nt][0], acc[mt][nt][1], acc[mt][nt][2], acc[mt][nt][3],
                             ah[mt][0], ah[mt][1], ah[mt][2], ah[mt][3],
                             bh[nt][0], bh[nt][1]);
            #pragma unroll
            for (int mt = 0; mt < 4; mt++)
                #pragma unroll
                for (int nt = 0; nt < 4; nt++)
                    mma16816(acc[mt][nt][0], acc[mt][nt][1], acc[mt][nt][2], acc[mt][nt][3],
                             ah[mt][0], ah[mt][1], ah[mt][2], ah[mt][3],
                             bl[nt][0], bl[nt][1]);
            #pragma unroll
            for (int mt = 0; mt < 4; mt++)
                #pragma unroll
                for (int nt = 0; nt < 4; nt++)
                    mma16816(acc[mt][nt][0], acc[mt][nt][1], acc[mt][nt][2], acc[mt][nt][3],
                             al[mt][0], al[mt][1], al[mt][2], al[mt][3],
                             bh[nt][0], bh[nt][1]);
        }

        if (c + 2 < 32) issue_chunk(c + 2);
    }

    __nv_bfloat16* ohi = z == 0 ? g_qhi : g_khi;
    __nv_bfloat16* olo = z == 0 ? g_qlo : g_klo;
    const float sc = (z == 0) ? SCQ : 1.0f;

    #pragma unroll
    for (int nt = 0; nt < 4; nt++) {
        const int n = n0 + wn * 32 + nt * 8 + fc;
        const int h = n >> 6;
        const int hd = n & 63;
        const float bv0 = bias[n];
        const float bv1 = bias[n + 1];
        #pragma unroll
        for (int mt = 0; mt < 4; mt++) {
            #pragma unroll
            for (int half = 0; half < 2; half++) {
                const int m = m0 + wm * 64 + mt * 16 + fr + half * 8;
                const int bb = m >> 10;
                const int s = m & 1023;
                float v0 = (acc[mt][nt][half * 2 + 0] + bv0) * sc;
                float v1 = (acc[mt][nt][half * 2 + 1] + bv1) * sc;
                if (z < 2) {
                    size_t idx = ((size_t)(bb * HH + h) * SS + s) * HD + hd;
                    __nv_bfloat162 hv = __floats2bfloat162_rn(v0, v1);
                    __nv_bfloat162 lv = __floats2bfloat162_rn(
                        v0 - __bfloat162float(hv.x), v1 - __bfloat162float(hv.y));
                    *(__nv_bfloat162*)(ohi + idx) = hv;
                    *(__nv_bfloat162*)(olo + idx) = lv;
                } else {
                    // V: write transposed [b,h,hd,s] bf16 hi/lo directly
                    const size_t tb = (size_t)(bb * HH + h) * HD;
                    __nv_bfloat16 h0 = __float2bfloat16(v0);
                    __nv_bfloat16 l0 = __float2bfloat16(v0 - __bfloat162float(h0));
                    __nv_bfloat16 h1 = __float2bfloat16(v1);
                    __nv_bfloat16 l1 = __float2bfloat16(v1 - __bfloat162float(h1));
                    g_vthi[(tb + hd) * SS + s]     = h0;
                    g_vtlo[(tb + hd) * SS + s]     = l0;
                    g_vthi[(tb + hd + 1) * SS + s] = h1;
                    g_vtlo[(tb + hd + 1) * SS + s] = l1;
                }
            }
        }
    }
}

// ---------------------------------------------------------------------------
// Pack adj into 1-bit mask and copy adj to second output region.
// ---------------------------------------------------------------------------
__global__ __launch_bounds__(256) void mask_pack(
    const float* __restrict__ adj, float* __restrict__ adj_out)
{
    int w = blockIdx.x * blockDim.x + threadIdx.x;
    const float4* a4 = (const float4*)adj;
    float4* o4 = (float4*)adj_out;
    unsigned bits = 0;
    #pragma unroll
    for (int i = 0; i < 8; i++) {
        float4 v = a4[(size_t)w * 8 + i];
        o4[(size_t)w * 8 + i] = v;
        bits |= (v.x >= 0.5f ? 1u : 0u) << (i * 4 + 0);
        bits |= (v.y >= 0.5f ? 1u : 0u) << (i * 4 + 1);
        bits |= (v.z >= 0.5f ? 1u : 0u) << (i * 4 + 2);
        bits |= (v.w >= 0.5f ? 1u : 0u) << (i * 4 + 3);
    }
    g_mask[w] = bits;
}

// ---------------------------------------------------------------------------
// Flash attention via mma.sync: q-tile 128, 256 threads, ldmatrix fragments.
// No-max softmax: scores pre-scaled by 0.125*log2(e); p = exp2(s [+NEG]).
// Lane-local l accumulation; single shfl-reduce in epilogue.
// ---------------------------------------------------------------------------
#define AQP 72
#define KT_ELEM (64 * AQP)
#define QT_ELEM (128 * AQP)

__global__ __launch_bounds__(256, 2) void attn_mma(float* __restrict__ out)
{
    extern __shared__ __nv_bfloat16 smp[];
    __nv_bfloat16* Qh = smp;
    __nv_bfloat16* Ql = Qh + QT_ELEM;
    __nv_bfloat16* KV = Ql + QT_ELEM;

    const int tid  = threadIdx.x;
    const int lane = tid & 31;
    const int warp = tid >> 5;
    const int g    = lane >> 2;
    const int t    = lane & 3;
    const int q0   = blockIdx.x * 128;
    const int h    = blockIdx.y;
    const int bb   = blockIdx.z;
    const int wq0  = warp * 16;

    const size_t bhs = ((size_t)(bb * HH + h)) * SS;
    const __nv_bfloat16* gqh = g_qhi + (bhs + q0) * HD;
    const __nv_bfloat16* gql = g_qlo + (bhs + q0) * HD;
    const __nv_bfloat16* gkh = g_khi + bhs * HD;
    const __nv_bfloat16* gkl = g_klo + bhs * HD;
    const __nv_bfloat16* gvh = g_vthi + ((size_t)(bb * HH + h)) * HD * SS;
    const __nv_bfloat16* gvl = g_vtlo + ((size_t)(bb * HH + h)) * HD * SS;

    const uint32_t sQh = smem_u32(Qh);
    const uint32_t sQl = smem_u32(Ql);
    const uint32_t sKV = smem_u32(KV);

    {
        #pragma unroll
        for (int j = 0; j < 4; j++) {
            int id  = tid + j * 256;
            int r   = id >> 3;
            int seg = id & 7;
            uint32_t doff = (uint32_t)(r * AQP + seg * 8) * 2;
            cp16(sQh + doff, gqh + (size_t)r * HD + seg * 8);
            cp16(sQl + doff, gql + (size_t)r * HD + seg * 8);
        }
        #pragma unroll
        for (int j = 0; j < 2; j++) {
            int id  = tid + j * 256;
            int r   = id >> 3;
            int seg = id & 7;
            uint32_t doff = (uint32_t)(r * AQP + seg * 8) * 2;
            cp16(sKV + 0 * KT_ELEM * 2 + doff, gkh + (size_t)r * HD + seg * 8);
            cp16(sKV + 1 * KT_ELEM * 2 + doff, gkl + (size_t)r * HD + seg * 8);
            cp16(sKV + 2 * KT_ELEM * 2 + doff, gvh + (size_t)r * SS + seg * 8);
            cp16(sKV + 3 * KT_ELEM * 2 + doff, gvl + (size_t)r * SS + seg * 8);
        }
        CP_COMMIT();
    }

    float o_acc[8][4];
    #pragma unroll
    for (int nt = 0; nt < 8; nt++)
        #pragma unroll
        for (int e = 0; e < 4; e++) o_acc[nt][e] = 0.f;
    float l0v = 0.f, l1v = 0.f;

    const unsigned* mrow = g_mask + (size_t)bb * SS * (SS / 32);
    const int r0g = q0 + wq0 + g;
    const int r1g = r0g + 8;

    const uint32_t a_row  = (uint32_t)(wq0 + (lane & 15));
    const uint32_t a_cofs = (uint32_t)((lane >> 4) << 3);
    const uint32_t b_rofs = (uint32_t)((lane & 7) + ((lane >> 4) << 3));
    const uint32_t b_cofs = (uint32_t)(((lane >> 3) & 1) << 3);

    for (int kt = 0; kt < 16; kt++) {
        const int cur = kt & 1;
        if (kt + 1 < 16) {
            const int nxt = (kt + 1) & 1;
            const uint32_t base = sKV + (uint32_t)(nxt * 4 * KT_ELEM) * 2;
            const size_t koff = (size_t)(kt + 1) * 64;
            #pragma unroll
            for (int j = 0; j < 2; j++) {
                int id  = tid + j * 256;
                int r   = id >> 3;
                int seg = id & 7;
                uint32_t doff = (uint32_t)(r * AQP + seg * 8) * 2;
                cp16(base + 0 * KT_ELEM * 2 + doff, gkh + (koff + r) * HD + seg * 8);
                cp16(base + 1 * KT_ELEM * 2 + doff, gkl + (koff + r) * HD + seg * 8);
                cp16(base + 2 * KT_ELEM * 2 + doff, gvh + (size_t)r * SS + koff + seg * 8);
                cp16(base + 3 * KT_ELEM * 2 + doff, gvl + (size_t)r * SS + koff + seg * 8);
            }
            CP_COMMIT();
            asm volatile("cp.async.wait_group 1;" ::: "memory");
        } else {
            asm volatile("cp.async.wait_group 0;" ::: "memory");
        }
        __syncthreads();

        const uint32_t sKh = sKV + (uint32_t)((cur * 4 + 0) * KT_ELEM) * 2;
        const uint32_t sKl = sKV + (uint32_t)((cur * 4 + 1) * KT_ELEM) * 2;
        const uint32_t sVh = sKV + (uint32_t)((cur * 4 + 2) * KT_ELEM) * 2;
        const uint32_t sVl = sKV + (uint32_t)((cur * 4 + 3) * KT_ELEM) * 2;

        // ---- S = Q K^T (3-term split), ldmatrix fragments ----
        float sf[8][4];
        #pragma unroll
        for (int nt = 0; nt < 8; nt++)
            #pragma unroll
            for (int e = 0; e < 4; e++) sf[nt][e] = 0.f;

        #pragma unroll
        for (int kk = 0; kk < 4; kk++) {
            const uint32_t kb = kk * 16;
            uint32_t qah[4], qal[4];
            const uint32_t aoff = (a_row * AQP + kb + a_cofs) * 2;
            ldm_x4(qah[0], qah[1], qah[2], qah[3], sQh + aoff);
            ldm_x4(qal[0], qal[1], qal[2], qal[3], sQl + aoff);
            #pragma unroll
            for (int np = 0; np < 4; np++) {
                uint32_t kh0, kh1, kh2, kh3, kl0, kl1, kl2, kl3;
                const uint32_t boff = ((np * 16 + b_rofs) * AQP + kb + b_cofs) * 2;
                ldm_x4(kh0, kh1, kh2, kh3, sKh + boff);
                ldm_x4(kl0, kl1, kl2, kl3, sKl + boff);
                float* d0 = sf[np * 2];
                float* d1 = sf[np * 2 + 1];
                mma16816(d0[0], d0[1], d0[2], d0[3], qah[0], qah[1], qah[2], qah[3], kh0, kh1);
                mma16816(d1[0], d1[1], d1[2], d1[3], qah[0], qah[1], qah[2], qah[3], kh2, kh3);
                mma16816(d0[0], d0[1], d0[2], d0[3], qah[0], qah[1], qah[2], qah[3], kl0, kl1);
                mma16816(d1[0], d1[1], d1[2], d1[3], qah[0], qah[1], qah[2], qah[3], kl2, kl3);
                mma16816(d0[0], d0[1], d0[2], d0[3], qal[0], qal[1], qal[2], qal[3], kh0, kh1);
                mma16816(d1[0], d1[1], d1[2], d1[3], qal[0], qal[1], qal[2], qal[3], kh2, kh3);
            }
        }

        // ---- mask + exp2 (no max subtraction), pack P to bf16 hi/lo ----
        const unsigned w0 = mrow[(size_t)r0g * 32 + kt * 2];
        const unsigned w1 = mrow[(size_t)r0g * 32 + kt * 2 + 1];
        const unsigned w2 = mrow[(size_t)r1g * 32 + kt * 2];
        const unsigned w3 = mrow[(size_t)r1g * 32 + kt * 2 + 1];

        uint32_t ph0[8], pl0[8], ph1[8], pl1[8];
        #pragma unroll
        for (int nt = 0; nt < 8; nt++) {
            const unsigned wa = nt < 4 ? w0 : w1;
            const unsigned wb = nt < 4 ? w2 : w3;
            const int sh = (nt & 3) * 8 + 2 * t;
            float p00 = exp2f(sf[nt][0] + (((wa >> sh) & 1u) ? 0.f : NEGV));
            float p01 = exp2f(sf[nt][1] + (((wa >> (sh + 1)) & 1u) ? 0.f : NEGV));
            float p10 = exp2f(sf[nt][2] + (((wb >> sh) & 1u) ? 0.f : NEGV));
            float p11 = exp2f(sf[nt][3] + (((wb >> (sh + 1)) & 1u) ? 0.f : NEGV));
            l0v += p00 + p01;
            l1v += p10 + p11;
            __nv_bfloat162 hv0 = __floats2bfloat162_rn(p00, p01);
            __nv_bfloat162 lv0 = __floats2bfloat162_rn(
                p00 - __bfloat162float(hv0.x), p01 - __bfloat162float(hv0.y));
            __nv_bfloat162 hv1 = __floats2bfloat162_rn(p10, p11);
            __nv_bfloat162 lv1 = __floats2bfloat162_rn(
                p10 - __bfloat162float(hv1.x), p11 - __bfloat162float(hv1.y));
            ph0[nt] = *(uint32_t*)&hv0; pl0[nt] = *(uint32_t*)&lv0;
            ph1[nt] = *(uint32_t*)&hv1; pl1[nt] = *(uint32_t*)&lv1;
        }

        // ---- O += P V (3-term split), ldmatrix V fragments ----
        #pragma unroll
        for (int kc = 0; kc < 4; kc++) {
            const uint32_t ah0 = ph0[2 * kc],     ah1 = ph1[2 * kc];
            const uint32_t ah2 = ph0[2 * kc + 1], ah3 = ph1[2 * kc + 1];
            const uint32_t al0 = pl0[2 * kc],     al1 = pl1[2 * kc];
            const uint32_t al2 = pl0[2 * kc + 1], al3 = pl1[2 * kc + 1];
            #pragma unroll
            for (int np = 0; np < 4; np++) {
                uint32_t vh0, vh1, vh2, vh3, vl0, vl1, vl2, vl3;
                const uint32_t boff = ((np * 16 + b_rofs) * AQP + kc * 16 + b_cofs) * 2;
                ldm_x4(vh0, vh1, vh2, vh3, sVh + boff);
                ldm_x4(vl0, vl1, vl2, vl3, sVl + boff);
                float* d0 = o_acc[np * 2];
                float* d1 = o_acc[np * 2 + 1];
                mma16816(d0[0], d0[1], d0[2], d0[3], ah0, ah1, ah2, ah3, vh0, vh1);
                mma16816(d1[0], d1[1], d1[2], d1[3], ah0, ah1, ah2, ah3, vh2, vh3);
                mma16816(d0[0], d0[1], d0[2], d0[3], ah0, ah1, ah2, ah3, vl0, vl1);
                mma16816(d1[0], d1[1], d1[2], d1[3], ah0, ah1, ah2, ah3, vl2, vl3);
                mma16816(d0[0], d0[1], d0[2], d0[3], al0, al1, al2, al3, vh0, vh1);
                mma16816(d1[0], d1[1], d1[2], d1[3], al0, al1, al2, al3, vh2, vh3);
            }
        }
        __syncthreads();
    }

    // ---- epilogue: reduce l across the 4-lane group, normalize, relu ----
    l0v += __shfl_xor_sync(0xffffffffu, l0v, 1);
    l0v += __shfl_xor_sync(0xffffffffu, l0v, 2);
    l1v += __shfl_xor_sync(0xffffffffu, l1v, 1);
    l1v += __shfl_xor_sync(0xffffffffu, l1v, 2);
    const float inv0 = 1.f / l0v;
    const float inv1 = 1.f / l1v;
    #pragma unroll
    for (int nt = 0; nt < 8; nt++) {
        const int col = h * 64 + nt * 8 + 2 * t;
        float2 oa, ob;
        oa.x = fmaxf(o_acc[nt][0] * inv0, 0.f);
        oa.y = fmaxf(o_acc[nt][1] * inv0, 0.f);
        ob.x = fmaxf(o_acc[nt][2] * inv1, 0.f);
        ob.y = fmaxf(o_acc[nt][3] * inv1, 0.f);
        *(float2*)(out + ((size_t)bb * SS + r0g) * DD + col) = oa;
        *(float2*)(out + ((size_t)bb * SS + r1g) * DD + col) = ob;
    }
}

// ---------------------------------------------------------------------------
extern "C" void kernel_launch(void* const* d_in, const int* in_sizes, int n_in,
                              void* d_out, int out_size)
{
    const float* x   = (const float*)d_in[0];
    const float* adj = (const float*)d_in[1];
    const float* Wq  = (const float*)d_in[2];
    const float* bq  = (const float*)d_in[3];
    const float* Wk  = (const float*)d_in[4];
    const float* bk  = (const float*)d_in[5];
    const float* Wv  = (const float*)d_in[6];
    const float* bv  = (const float*)d_in[7];

    float* out     = (float*)d_out;
    float* out_adj = out + (size_t)BB * SS * DD;

    conv_x<<<(BB * SS * DD) / (256 * 4), 256>>>(x);
    conv_w<<<dim3(DD / 32, DD / 32, 3), dim3(32, 8)>>>(Wq, Wk, Wv);
    mask_pack<<<(BB * SS * (SS / 32)) / 256, 256>>>(adj, out_adj);

    cudaFuncSetAttribute(qkv_gemm_mma, cudaFuncAttributeMaxDynamicSharedMemorySize, GSMB);
    qkv_gemm_mma<<<dim3(DD / 128, (BB * SS) / 128, 3), 256, GSMB>>>(bq, bk, bv);

    const int attn_smem = (2 * QT_ELEM + 8 * KT_ELEM) * (int)sizeof(__nv_bfloat16);
    cudaFuncSetAttribute(attn_mma, cudaFuncAttributeMaxDynamicSharedMemorySize, attn_smem);
    attn_mma<<<dim3(SS / 128, HH, BB), 256, attn_smem>>>(out);
}

// round 13
// speedup vs baseline: 1.0803x; 1.0175x over previous
#include <cuda_runtime.h>
#include <cuda_bf16.h>
#include <cstdint>

#define BB 4
#define SS 1024
#define DD 1024
#define HH 16
#define HD 64
#define NEGV -10000000.0f
#define SCQ 0.18033688011112042f   /* 0.125 * log2(e) */

// ---------------------------------------------------------------------------
// Scratch (__device__ globals; no allocation allowed)
// ---------------------------------------------------------------------------
__device__ unsigned g_mask[BB*SS*(SS/32)];
__device__ __nv_bfloat16 g_xhi[BB*SS*DD];
__device__ __nv_bfloat16 g_xlo[BB*SS*DD];
__device__ __nv_bfloat16 g_whi[3][DD*DD];          // transposed: [n][k]
__device__ __nv_bfloat16 g_wlo[3][DD*DD];
__device__ __nv_bfloat16 g_qhi[BB*HH*SS*HD];       // [b,h,s,hd] (pre-scaled by SCQ)
__device__ __nv_bfloat16 g_qlo[BB*HH*SS*HD];
__device__ __nv_bfloat16 g_khi[BB*HH*SS*HD];       // [b,h,s,hd]
__device__ __nv_bfloat16 g_klo[BB*HH*SS*HD];
__device__ __nv_bfloat16 g_vthi[BB*HH*HD*SS];      // [b,h,hd,s]  (transposed)
__device__ __nv_bfloat16 g_vtlo[BB*HH*HD*SS];

// ---------------------------------------------------------------------------
// PTX helpers (baseline PTX only — works on plain sm_103 target)
// ---------------------------------------------------------------------------
__device__ __forceinline__ void mma16816(
    float& d0, float& d1, float& d2, float& d3,
    uint32_t a0, uint32_t a1, uint32_t a2, uint32_t a3,
    uint32_t b0, uint32_t b1)
{
    asm volatile(
        "mma.sync.aligned.m16n8k16.row.col.f32.bf16.bf16.f32 "
        "{%0,%1,%2,%3}, {%4,%5,%6,%7}, {%8,%9}, {%0,%1,%2,%3};"
        : "+f"(d0), "+f"(d1), "+f"(d2), "+f"(d3)
        : "r"(a0), "r"(a1), "r"(a2), "r"(a3), "r"(b0), "r"(b1));
}

__device__ __forceinline__ void ldm_x4(
    uint32_t& r0, uint32_t& r1, uint32_t& r2, uint32_t& r3, uint32_t addr)
{
    asm volatile("ldmatrix.sync.aligned.m8n8.x4.shared.b16 {%0,%1,%2,%3}, [%4];"
        : "=r"(r0), "=r"(r1), "=r"(r2), "=r"(r3) : "r"(addr));
}

__device__ __forceinline__ uint32_t smem_u32(const void* p) {
    uint32_t a;
    asm("{ .reg .u64 t; cvta.to.shared.u64 t, %1; cvt.u32.u64 %0, t; }"
        : "=r"(a) : "l"(p));
    return a;
}

__device__ __forceinline__ void cp16(uint32_t dst, const void* src) {
    asm volatile("cp.async.cg.shared.global [%0], [%1], 16;" :: "r"(dst), "l"(src));
}
#define CP_COMMIT() asm volatile("cp.async.commit_group;" ::: "memory")

// ---------------------------------------------------------------------------
// Prep: split x into bf16 hi/lo
// ---------------------------------------------------------------------------
__global__ __launch_bounds__(256) void conv_x(const float* __restrict__ x)
{
    size_t i = ((size_t)blockIdx.x * 256 + threadIdx.x) * 4;
    float4 v = *(const float4*)(x + i);
    __nv_bfloat16 h0 = __float2bfloat16(v.x);
    __nv_bfloat16 h1 = __float2bfloat16(v.y);
    __nv_bfloat16 h2 = __float2bfloat16(v.z);
    __nv_bfloat16 h3 = __float2bfloat16(v.w);
    __nv_bfloat16 l0 = __float2bfloat16(v.x - __bfloat162float(h0));
    __nv_bfloat16 l1 = __float2bfloat16(v.y - __bfloat162float(h1));
    __nv_bfloat16 l2 = __float2bfloat16(v.z - __bfloat162float(h2));
    __nv_bfloat16 l3 = __float2bfloat16(v.w - __bfloat162float(h3));
    __nv_bfloat162 p;
    p.x = h0; p.y = h1; *(__nv_bfloat162*)(g_xhi + i)     = p;
    p.x = h2; p.y = h3; *(__nv_bfloat162*)(g_xhi + i + 2) = p;
    p.x = l0; p.y = l1; *(__nv_bfloat162*)(g_xlo + i)     = p;
    p.x = l2; p.y = l3; *(__nv_bfloat162*)(g_xlo + i + 2) = p;
}

// ---------------------------------------------------------------------------
// Prep: transpose W [K,N] -> Wt [N,K], split hi/lo
// ---------------------------------------------------------------------------
__global__ __launch_bounds__(256) void conv_w(
    const float* __restrict__ Wq, const float* __restrict__ Wk, const float* __restrict__ Wv)
{
    const int z = blockIdx.z;
    const float* W = z == 0 ? Wq : (z == 1 ? Wk : Wv);
    __shared__ float t[32][33];
    int tx = threadIdx.x, ty = threadIdx.y;
    int n0 = blockIdx.x * 32, k0 = blockIdx.y * 32;
    #pragma unroll
    for (int r = 0; r < 4; r++) {
        int k = k0 + ty + r * 8;
        t[ty + r * 8][tx] = W[(size_t)k * DD + n0 + tx];
    }
    __syncthreads();
    #pragma unroll
    for (int r = 0; r < 4; r++) {
        int nn = n0 + ty + r * 8;
        int kk = k0 + tx;
        float v = t[tx][ty + r * 8];
        __nv_bfloat16 hi = __float2bfloat16(v);
        __nv_bfloat16 lo = __float2bfloat16(v - __bfloat162float(hi));
        g_whi[z][(size_t)nn * DD + kk] = hi;
        g_wlo[z][(size_t)nn * DD + kk] = lo;
    }
}

// ---------------------------------------------------------------------------
// QKV GEMM via mma.sync + 3-stage cp.async pipeline (single barrier/chunk).
// Q epilogue pre-scales by SCQ; V epilogue writes transposed bf16 hi/lo.
// ---------------------------------------------------------------------------
#define GT2   (128 * 32)
#define NSTG  3
#define GSMB  (NSTG * 4 * GT2 * 2)

__device__ __forceinline__ uint32_t gsw(int row, int chunk) {
    return (uint32_t)(row * 64 + ((chunk ^ ((row >> 1) & 3)) << 4));
}

__global__ __launch_bounds__(256, 2) void qkv_gemm_mma(
    const float* __restrict__ bq, const float* __restrict__ bk, const float* __restrict__ bv)
{
    extern __shared__ __nv_bfloat16 gsm[];

    const int tid  = threadIdx.x;
    const int lane = tid & 31;
    const int wid  = tid >> 5;
    const int wm   = wid >> 2;
    const int wn   = wid & 3;
    const int z    = blockIdx.z;
    const int m0   = blockIdx.y * 128;
    const int n0   = blockIdx.x * 128;

    const __nv_bfloat16* __restrict__ gAh = g_xhi;
    const __nv_bfloat16* __restrict__ gAl = g_xlo;
    const __nv_bfloat16* __restrict__ gBh = g_whi[z];
    const __nv_bfloat16* __restrict__ gBl = g_wlo[z];
    const float* bias = z == 0 ? bq : (z == 1 ? bk : bv);

    const uint32_t sb = smem_u32(gsm);

    float acc[4][4][4];
    #pragma unroll
    for (int mt = 0; mt < 4; mt++)
        #pragma unroll
        for (int nt = 0; nt < 4; nt++)
            #pragma unroll
            for (int r = 0; r < 4; r++) acc[mt][nt][r] = 0.f;

    const int fr = lane >> 2;
    const int fc = (lane & 3) * 2;

    auto issue_chunk = [&](int c) {
        const uint32_t base = sb + (uint32_t)((c % NSTG) * 4 * GT2) * 2;
        const int k0 = c * 32;
        #pragma unroll
        for (int i = 0; i < 2; i++) {
            const int idx = tid + i * 256;
            const int row = idx >> 2;
            const int seg = idx & 3;
            const uint32_t doff = gsw(row, seg);
            const size_t ao = (size_t)(m0 + row) * DD + k0 + seg * 8;
            const size_t bo = (size_t)(n0 + row) * DD + k0 + seg * 8;
            cp16(base + 0u * GT2 * 2 + doff, gAh + ao);
            cp16(base + 1u * GT2 * 2 + doff, gAl + ao);
            cp16(base + 2u * GT2 * 2 + doff, gBh + bo);
            cp16(base + 3u * GT2 * 2 + doff, gBl + bo);
        }
        CP_COMMIT();
    };

    issue_chunk(0);
    issue_chunk(1);

    for (int c = 0; c < 32; c++) {
        if (c < 30) asm volatile("cp.async.wait_group 1;" ::: "memory");
        else        asm volatile("cp.async.wait_group 0;" ::: "memory");
        __syncthreads();

        const uint32_t sbase = sb + (uint32_t)((c % NSTG) * 4 * GT2) * 2;
        #pragma unroll
        for (int ks = 0; ks < 2; ks++) {
            const int kc = ks * 2;
            uint32_t ah[4][4], al[4][4], bh[4][2], bl[4][2];
            #pragma unroll
            for (int mt = 0; mt < 4; mt++) {
                const int row = wm * 64 + mt * 16 + (lane & 15);
                const uint32_t aoff = gsw(row, kc + (lane >> 4));
                ldm_x4(ah[mt][0], ah[mt][1], ah[mt][2], ah[mt][3],
                       sbase + 0u * GT2 * 2 + aoff);
                ldm_x4(al[mt][0], al[mt][1], al[mt][2], al[mt][3],
                       sbase + 1u * GT2 * 2 + aoff);
            }
            #pragma unroll
            for (int np = 0; np < 2; np++) {
                const int row = wn * 32 + np * 16 + (lane & 7) + ((lane >> 4) << 3);
                const uint32_t boff = gsw(row, kc + ((lane >> 3) & 1));
                ldm_x4(bh[np * 2][0], bh[np * 2][1], bh[np * 2 + 1][0], bh[np * 2 + 1][1],
                       sbase + 2u * GT2 * 2 + boff);
                ldm_x4(bl[np * 2][0], bl[np * 2][1], bl[np * 2 + 1][0], bl[np * 2 + 1][1],
                       sbase + 3u * GT2 * 2 + boff);
            }
            #pragma unroll
            for (int mt = 0; mt < 4; mt++)
                #pragma unroll
                for (int nt = 0; nt < 4; nt++)
                    mma16816(acc[mt][nt][0], acc[mt][nt][1], acc[mt][nt][2], acc[mt][nt][3],
                             ah[mt][0], ah[mt][1], ah[mt][2], ah[mt][3],
                             bh[nt][0], bh[nt][1]);
            #pragma unroll
            for (int mt = 0; mt < 4; mt++)
                #pragma unroll
                for (int nt = 0; nt < 4; nt++)
                    mma16816(acc[mt][nt][0], acc[mt][nt][1], acc[mt][nt][2], acc[mt][nt][3],
                             ah[mt][0], ah[mt][1], ah[mt][2], ah[mt][3],
                             bl[nt][0], bl[nt][1]);
            #pragma unroll
            for (int mt = 0; mt < 4; mt++)
                #pragma unroll
                for (int nt = 0; nt < 4; nt++)
                    mma16816(acc[mt][nt][0], acc[mt][nt][1], acc[mt][nt][2], acc[mt][nt][3],
                             al[mt][0], al[mt][1], al[mt][2], al[mt][3],
                             bh[nt][0], bh[nt][1]);
        }

        if (c + 2 < 32) issue_chunk(c + 2);
    }

    __nv_bfloat16* ohi = z == 0 ? g_qhi : g_khi;
    __nv_bfloat16* olo = z == 0 ? g_qlo : g_klo;
    const float sc = (z == 0) ? SCQ : 1.0f;

    #pragma unroll
    for (int nt = 0; nt < 4; nt++) {
        const int n = n0 + wn * 32 + nt * 8 + fc;
        const int h = n >> 6;
        const int hd = n & 63;
        const float bv0 = bias[n];
        const float bv1 = bias[n + 1];
        #pragma unroll
        for (int mt = 0; mt < 4; mt++) {
            #pragma unroll
            for (int half = 0; half < 2; half++) {
                const int m = m0 + wm * 64 + mt * 16 + fr + half * 8;
                const int bb = m >> 10;
                const int s = m & 1023;
                float v0 = (acc[mt][nt][half * 2 + 0] + bv0) * sc;
                float v1 = (acc[mt][nt][half * 2 + 1] + bv1) * sc;
                if (z < 2) {
                    size_t idx = ((size_t)(bb * HH + h) * SS + s) * HD + hd;
                    __nv_bfloat162 hv = __floats2bfloat162_rn(v0, v1);
                    __nv_bfloat162 lv = __floats2bfloat162_rn(
                        v0 - __bfloat162float(hv.x), v1 - __bfloat162float(hv.y));
                    *(__nv_bfloat162*)(ohi + idx) = hv;
                    *(__nv_bfloat162*)(olo + idx) = lv;
                } else {
                    const size_t tb = (size_t)(bb * HH + h) * HD;
                    __nv_bfloat16 h0 = __float2bfloat16(v0);
                    __nv_bfloat16 l0 = __float2bfloat16(v0 - __bfloat162float(h0));
                    __nv_bfloat16 h1 = __float2bfloat16(v1);
                    __nv_bfloat16 l1 = __float2bfloat16(v1 - __bfloat162float(h1));
                    g_vthi[(tb + hd) * SS + s]     = h0;
                    g_vtlo[(tb + hd) * SS + s]     = l0;
                    g_vthi[(tb + hd + 1) * SS + s] = h1;
                    g_vtlo[(tb + hd + 1) * SS + s] = l1;
                }
            }
        }
    }
}

// ---------------------------------------------------------------------------
// Pack adj into 1-bit mask and copy adj to second output region.
// ---------------------------------------------------------------------------
__global__ __launch_bounds__(256) void mask_pack(
    const float* __restrict__ adj, float* __restrict__ adj_out)
{
    int w = blockIdx.x * blockDim.x + threadIdx.x;
    const float4* a4 = (const float4*)adj;
    float4* o4 = (float4*)adj_out;
    unsigned bits = 0;
    #pragma unroll
    for (int i = 0; i < 8; i++) {
        float4 v = a4[(size_t)w * 8 + i];
        o4[(size_t)w * 8 + i] = v;
        bits |= (v.x >= 0.5f ? 1u : 0u) << (i * 4 + 0);
        bits |= (v.y >= 0.5f ? 1u : 0u) << (i * 4 + 1);
        bits |= (v.z >= 0.5f ? 1u : 0u) << (i * 4 + 2);
        bits |= (v.w >= 0.5f ? 1u : 0u) << (i * 4 + 3);
    }
    g_mask[w] = bits;
}

// ---------------------------------------------------------------------------
// Flash attention via mma.sync: q-tile 128, 256 threads, ldmatrix fragments.
// No-max softmax: scores pre-scaled by 0.125*log2(e); p = exp2(s [+NEG]).
// ---------------------------------------------------------------------------
#define AQP 72
#define KT_ELEM (64 * AQP)
#define QT_ELEM (128 * AQP)

__global__ __launch_bounds__(256, 2) void attn_mma(float* __restrict__ out)
{
    extern __shared__ __nv_bfloat16 smp[];
    __nv_bfloat16* Qh = smp;
    __nv_bfloat16* Ql = Qh + QT_ELEM;
    __nv_bfloat16* KV = Ql + QT_ELEM;

    const int tid  = threadIdx.x;
    const int lane = tid & 31;
    const int warp = tid >> 5;
    const int g    = lane >> 2;
    const int t    = lane & 3;
    const int q0   = blockIdx.x * 128;
    const int h    = blockIdx.y;
    const int bb   = blockIdx.z;
    const int wq0  = warp * 16;

    const size_t bhs = ((size_t)(bb * HH + h)) * SS;
    const __nv_bfloat16* gqh = g_qhi + (bhs + q0) * HD;
    const __nv_bfloat16* gql = g_qlo + (bhs + q0) * HD;
    const __nv_bfloat16* gkh = g_khi + bhs * HD;
    const __nv_bfloat16* gkl = g_klo + bhs * HD;
    const __nv_bfloat16* gvh = g_vthi + ((size_t)(bb * HH + h)) * HD * SS;
    const __nv_bfloat16* gvl = g_vtlo + ((size_t)(bb * HH + h)) * HD * SS;

    const uint32_t sQh = smem_u32(Qh);
    const uint32_t sQl = smem_u32(Ql);
    const uint32_t sKV = smem_u32(KV);

    {
        #pragma unroll
        for (int j = 0; j < 4; j++) {
            int id  = tid + j * 256;
            int r   = id >> 3;
            int seg = id & 7;
            uint32_t doff = (uint32_t)(r * AQP + seg * 8) * 2;
            cp16(sQh + doff, gqh + (size_t)r * HD + seg * 8);
            cp16(sQl + doff, gql + (size_t)r * HD + seg * 8);
        }
        #pragma unroll
        for (int j = 0; j < 2; j++) {
            int id  = tid + j * 256;
            int r   = id >> 3;
            int seg = id & 7;
            uint32_t doff = (uint32_t)(r * AQP + seg * 8) * 2;
            cp16(sKV + 0 * KT_ELEM * 2 + doff, gkh + (size_t)r * HD + seg * 8);
            cp16(sKV + 1 * KT_ELEM * 2 + doff, gkl + (size_t)r * HD + seg * 8);
            cp16(sKV + 2 * KT_ELEM * 2 + doff, gvh + (size_t)r * SS + seg * 8);
            cp16(sKV + 3 * KT_ELEM * 2 + doff, gvl + (size_t)r * SS + seg * 8);
        }
        CP_COMMIT();
    }

    float o_acc[8][4];
    #pragma unroll
    for (int nt = 0; nt < 8; nt++)
        #pragma unroll
        for (int e = 0; e < 4; e++) o_acc[nt][e] = 0.f;
    float l0v = 0.f, l1v = 0.f;

    const unsigned* mrow = g_mask + (size_t)bb * SS * (SS / 32);
    const int r0g = q0 + wq0 + g;
    const int r1g = r0g + 8;

    const uint32_t a_row  = (uint32_t)(wq0 + (lane & 15));
    const uint32_t a_cofs = (uint32_t)((lane >> 4) << 3);
    const uint32_t b_rofs = (uint32_t)((lane & 7) + ((lane >> 4) << 3));
    const uint32_t b_cofs = (uint32_t)(((lane >> 3) & 1) << 3);

    for (int kt = 0; kt < 16; kt++) {
        const int cur = kt & 1;
        if (kt + 1 < 16) {
            const int nxt = (kt + 1) & 1;
            const uint32_t base = sKV + (uint32_t)(nxt * 4 * KT_ELEM) * 2;
            const size_t koff = (size_t)(kt + 1) * 64;
            #pragma unroll
            for (int j = 0; j < 2; j++) {
                int id  = tid + j * 256;
                int r   = id >> 3;
                int seg = id & 7;
                uint32_t doff = (uint32_t)(r * AQP + seg * 8) * 2;
                cp16(base + 0 * KT_ELEM * 2 + doff, gkh + (koff + r) * HD + seg * 8);
                cp16(base + 1 * KT_ELEM * 2 + doff, gkl + (koff + r) * HD + seg * 8);
                cp16(base + 2 * KT_ELEM * 2 + doff, gvh + (size_t)r * SS + koff + seg * 8);
                cp16(base + 3 * KT_ELEM * 2 + doff, gvl + (size_t)r * SS + koff + seg * 8);
            }
            CP_COMMIT();
            asm volatile("cp.async.wait_group 1;" ::: "memory");
        } else {
            asm volatile("cp.async.wait_group 0;" ::: "memory");
        }
        __syncthreads();

        const uint32_t sKh = sKV + (uint32_t)((cur * 4 + 0) * KT_ELEM) * 2;
        const uint32_t sKl = sKV + (uint32_t)((cur * 4 + 1) * KT_ELEM) * 2;
        const uint32_t sVh = sKV + (uint32_t)((cur * 4 + 2) * KT_ELEM) * 2;
        const uint32_t sVl = sKV + (uint32_t)((cur * 4 + 3) * KT_ELEM) * 2;

        float sf[8][4];
        #pragma unroll
        for (int nt = 0; nt < 8; nt++)
            #pragma unroll
            for (int e = 0; e < 4; e++) sf[nt][e] = 0.f;

        #pragma unroll
        for (int kk = 0; kk < 4; kk++) {
            const uint32_t kb = kk * 16;
            uint32_t qah[4], qal[4];
            const uint32_t aoff = (a_row * AQP + kb + a_cofs) * 2;
            ldm_x4(qah[0], qah[1], qah[2], qah[3], sQh + aoff);
            ldm_x4(qal[0], qal[1], qal[2], qal[3], sQl + aoff);
            #pragma unroll
            for (int np = 0; np < 4; np++) {
                uint32_t kh0, kh1, kh2, kh3, kl0, kl1, kl2, kl3;
                const uint32_t boff = ((np * 16 + b_rofs) * AQP + kb + b_cofs) * 2;
                ldm_x4(kh0, kh1, kh2, kh3, sKh + boff);
                ldm_x4(kl0, kl1, kl2, kl3, sKl + boff);
                float* d0 = sf[np * 2];
                float* d1 = sf[np * 2 + 1];
                mma16816(d0[0], d0[1], d0[2], d0[3], qah[0], qah[1], qah[2], qah[3], kh0, kh1);
                mma16816(d1[0], d1[1], d1[2], d1[3], qah[0], qah[1], qah[2], qah[3], kh2, kh3);
                mma16816(d0[0], d0[1], d0[2], d0[3], qah[0], qah[1], qah[2], qah[3], kl0, kl1);
                mma16816(d1[0], d1[1], d1[2], d1[3], qah[0], qah[1], qah[2], qah[3], kl2, kl3);
                mma16816(d0[0], d0[1], d0[2], d0[3], qal[0], qal[1], qal[2], qal[3], kh0, kh1);
                mma16816(d1[0], d1[1], d1[2], d1[3], qal[0], qal[1], qal[2], qal[3], kh2, kh3);
            }
        }

        const unsigned w0 = mrow[(size_t)r0g * 32 + kt * 2];
        const unsigned w1 = mrow[(size_t)r0g * 32 + kt * 2 + 1];
        const unsigned w2 = mrow[(size_t)r1g * 32 + kt * 2];
        const unsigned w3 = mrow[(size_t)r1g * 32 + kt * 2 + 1];

        uint32_t ph0[8], pl0[8], ph1[8], pl1[8];
        #pragma unroll
        for (int nt = 0; nt < 8; nt++) {
            const unsigned wa = nt < 4 ? w0 : w1;
            const unsigned wb = nt < 4 ? w2 : w3;
            const int sh = (nt & 3) * 8 + 2 * t;
            float p00 = exp2f(sf[nt][0] + (((wa >> sh) & 1u) ? 0.f : NEGV));
            float p01 = exp2f(sf[nt][1] + (((wa >> (sh + 1)) & 1u) ? 0.f : NEGV));
            float p10 = exp2f(sf[nt][2] + (((wb >> sh) & 1u) ? 0.f : NEGV));
            float p11 = exp2f(sf[nt][3] + (((wb >> (sh + 1)) & 1u) ? 0.f : NEGV));
            l0v += p00 + p01;
            l1v += p10 + p11;
            __nv_bfloat162 hv0 = __floats2bfloat162_rn(p00, p01);
            __nv_bfloat162 lv0 = __floats2bfloat162_rn(
                p00 - __bfloat162float(hv0.x), p01 - __bfloat162float(hv0.y));
            __nv_bfloat162 hv1 = __floats2bfloat162_rn(p10, p11);
            __nv_bfloat162 lv1 = __floats2bfloat162_rn(
                p10 - __bfloat162float(hv1.x), p11 - __bfloat162float(hv1.y));
            ph0[nt] = *(uint32_t*)&hv0; pl0[nt] = *(uint32_t*)&lv0;
            ph1[nt] = *(uint32_t*)&hv1; pl1[nt] = *(uint32_t*)&lv1;
        }

        #pragma unroll
        for (int kc = 0; kc < 4; kc++) {
            const uint32_t ah0 = ph0[2 * kc],     ah1 = ph1[2 * kc];
            const uint32_t ah2 = ph0[2 * kc + 1], ah3 = ph1[2 * kc + 1];
            const uint32_t al0 = pl0[2 * kc],     al1 = pl1[2 * kc];
            const uint32_t al2 = pl0[2 * kc + 1], al3 = pl1[2 * kc + 1];
            #pragma unroll
            for (int np = 0; np < 4; np++) {
                uint32_t vh0, vh1, vh2, vh3, vl0, vl1, vl2, vl3;
                const uint32_t boff = ((np * 16 + b_rofs) * AQP + kc * 16 + b_cofs) * 2;
                ldm_x4(vh0, vh1, vh2, vh3, sVh + boff);
                ldm_x4(vl0, vl1, vl2, vl3, sVl + boff);
                float* d0 = o_acc[np * 2];
                float* d1 = o_acc[np * 2 + 1];
                mma16816(d0[0], d0[1], d0[2], d0[3], ah0, ah1, ah2, ah3, vh0, vh1);
                mma16816(d1[0], d1[1], d1[2], d1[3], ah0, ah1, ah2, ah3, vh2, vh3);
                mma16816(d0[0], d0[1], d0[2], d0[3], ah0, ah1, ah2, ah3, vl0, vl1);
                mma16816(d1[0], d1[1], d1[2], d1[3], ah0, ah1, ah2, ah3, vl2, vl3);
                mma16816(d0[0], d0[1], d0[2], d0[3], al0, al1, al2, al3, vh0, vh1);
                mma16816(d1[0], d1[1], d1[2], d1[3], al0, al1, al2, al3, vh2, vh3);
            }
        }
        __syncthreads();
    }

    l0v += __shfl_xor_sync(0xffffffffu, l0v, 1);
    l0v += __shfl_xor_sync(0xffffffffu, l0v, 2);
    l1v += __shfl_xor_sync(0xffffffffu, l1v, 1);
    l1v += __shfl_xor_sync(0xffffffffu, l1v, 2);
    const float inv0 = 1.f / l0v;
    const float inv1 = 1.f / l1v;
    #pragma unroll
    for (int nt = 0; nt < 8; nt++) {
        const int col = h * 64 + nt * 8 + 2 * t;
        float2 oa, ob;
        oa.x = fmaxf(o_acc[nt][0] * inv0, 0.f);
        oa.y = fmaxf(o_acc[nt][1] * inv0, 0.f);
        ob.x = fmaxf(o_acc[nt][2] * inv1, 0.f);
        ob.y = fmaxf(o_acc[nt][3] * inv1, 0.f);
        *(float2*)(out + ((size_t)bb * SS + r0g) * DD + col) = oa;
        *(float2*)(out + ((size_t)bb * SS + r1g) * DD + col) = ob;
    }
}

// ---------------------------------------------------------------------------
// Launch: fork/join side stream so mask_pack + conv_w overlap the GEMM.
//   main: conv_x -> (wait evW) qkv_gemm -> (wait evM) attn
//   side: conv_w (rec evW) -> mask_pack (rec evM)
// Streams/events created once on the first (uncaptured correctness) call;
// every call performs identical work.
// ---------------------------------------------------------------------------
extern "C" void kernel_launch(void* const* d_in, const int* in_sizes, int n_in,
                              void* d_out, int out_size)
{
    const float* x   = (const float*)d_in[0];
    const float* adj = (const float*)d_in[1];
    const float* Wq  = (const float*)d_in[2];
    const float* bq  = (const float*)d_in[3];
    const float* Wk  = (const float*)d_in[4];
    const float* bk  = (const float*)d_in[5];
    const float* Wv  = (const float*)d_in[6];
    const float* bv  = (const float*)d_in[7];

    float* out     = (float*)d_out;
    float* out_adj = out + (size_t)BB * SS * DD;

    static cudaStream_t side = nullptr;
    static cudaEvent_t evF = nullptr, evW = nullptr, evM = nullptr;
    static bool attrs_set = false;
    if (side == nullptr) {
        cudaStreamCreateWithFlags(&side, cudaStreamNonBlocking);
        cudaEventCreateWithFlags(&evF, cudaEventDisableTiming);
        cudaEventCreateWithFlags(&evW, cudaEventDisableTiming);
        cudaEventCreateWithFlags(&evM, cudaEventDisableTiming);
    }
    if (!attrs_set) {
        cudaFuncSetAttribute(qkv_gemm_mma, cudaFuncAttributeMaxDynamicSharedMemorySize, GSMB);
        cudaFuncSetAttribute(attn_mma, cudaFuncAttributeMaxDynamicSharedMemorySize,
                             (2 * QT_ELEM + 8 * KT_ELEM) * (int)sizeof(__nv_bfloat16));
        attrs_set = true;
    }

    // fork: side stream joins after current point on the main (legacy) stream
    cudaEventRecord(evF, 0);
    cudaStreamWaitEvent(side, evF, 0);

    // side: conv_w, then mask_pack
    conv_w<<<dim3(DD / 32, DD / 32, 3), dim3(32, 8), 0, side>>>(Wq, Wk, Wv);
    cudaEventRecord(evW, side);
    mask_pack<<<(BB * SS * (SS / 32)) / 256, 256, 0, side>>>(adj, out_adj);
    cudaEventRecord(evM, side);

    // main: conv_x, then GEMM (needs conv_w), then attn (needs mask_pack)
    conv_x<<<(BB * SS * DD) / (256 * 4), 256>>>(x);
    cudaStreamWaitEvent(0, evW, 0);
    qkv_gemm_mma<<<dim3(DD / 128, (BB * SS) / 128, 3), 256, GSMB>>>(bq, bk, bv);
    cudaStreamWaitEvent(0, evM, 0);

    const int attn_smem = (2 * QT_ELEM + 8 * KT_ELEM) * (int)sizeof(__nv_bfloat16);
    attn_mma<<<dim3(SS / 128, HH, BB), 256, attn_smem>>>(out);
}

// round 15
// speedup vs baseline: 1.5155x; 1.4029x over previous
#include <cuda_runtime.h>
#include <cuda_fp16.h>
#include <cstdint>

#define BB 4
#define SS 1024
#define DD 1024
#define HH 16
#define HD 64
#define NEGV -10000000.0f
#define SCQ 0.18033688011112042f   /* 0.125 * log2(e) */

// ---------------------------------------------------------------------------
// Scratch (__device__ globals; no allocation allowed)
// ---------------------------------------------------------------------------
__device__ unsigned g_mask[BB*SS*(SS/32)];
__device__ __half g_x[BB*SS*DD];              // x, single fp16
__device__ __half g_wh[3][DD*DD];             // W transposed [n][k], fp16 hi
__device__ __half g_wl[3][DD*DD];             // fp16 lo
__device__ __half g_qh[BB*HH*SS*HD];          // Q pair (pre-scaled by SCQ)
__device__ __half g_ql[BB*HH*SS*HD];
__device__ __half g_k[BB*HH*SS*HD];           // K single
__device__ __half g_vth[BB*HH*HD*SS];         // V^T pair [b,h,hd,s]
__device__ __half g_vtl[BB*HH*HD*SS];

// ---------------------------------------------------------------------------
// PTX helpers (baseline PTX only — works on plain sm_103 target)
// ---------------------------------------------------------------------------
__device__ __forceinline__ void mma16816(
    float& d0, float& d1, float& d2, float& d3,
    uint32_t a0, uint32_t a1, uint32_t a2, uint32_t a3,
    uint32_t b0, uint32_t b1)
{
    asm volatile(
        "mma.sync.aligned.m16n8k16.row.col.f32.f16.f16.f32 "
        "{%0,%1,%2,%3}, {%4,%5,%6,%7}, {%8,%9}, {%0,%1,%2,%3};"
        : "+f"(d0), "+f"(d1), "+f"(d2), "+f"(d3)
        : "r"(a0), "r"(a1), "r"(a2), "r"(a3), "r"(b0), "r"(b1));
}

__device__ __forceinline__ void ldm_x4(
    uint32_t& r0, uint32_t& r1, uint32_t& r2, uint32_t& r3, uint32_t addr)
{
    asm volatile("ldmatrix.sync.aligned.m8n8.x4.shared.b16 {%0,%1,%2,%3}, [%4];"
        : "=r"(r0), "=r"(r1), "=r"(r2), "=r"(r3) : "r"(addr));
}

__device__ __forceinline__ uint32_t smem_u32(const void* p) {
    uint32_t a;
    asm("{ .reg .u64 t; cvta.to.shared.u64 t, %1; cvt.u32.u64 %0, t; }"
        : "=r"(a) : "l"(p));
    return a;
}

__device__ __forceinline__ void cp16(uint32_t dst, const void* src) {
    asm volatile("cp.async.cg.shared.global [%0], [%1], 16;" :: "r"(dst), "l"(src));
}
#define CP_COMMIT() asm volatile("cp.async.commit_group;" ::: "memory")

// ---------------------------------------------------------------------------
// Prep: x -> single fp16
// ---------------------------------------------------------------------------
__global__ __launch_bounds__(256) void conv_x(const float* __restrict__ x)
{
    size_t i = ((size_t)blockIdx.x * 256 + threadIdx.x) * 4;
    float4 v = *(const float4*)(x + i);
    __half2 a = __floats2half2_rn(v.x, v.y);
    __half2 b = __floats2half2_rn(v.z, v.w);
    *(__half2*)(g_x + i)     = a;
    *(__half2*)(g_x + i + 2) = b;
}

// ---------------------------------------------------------------------------
// Prep: transpose W [K,N] -> Wt [N,K], split fp16 hi/lo
// ---------------------------------------------------------------------------
__global__ __launch_bounds__(256) void conv_w(
    const float* __restrict__ Wq, const float* __restrict__ Wk, const float* __restrict__ Wv)
{
    const int z = blockIdx.z;
    const float* W = z == 0 ? Wq : (z == 1 ? Wk : Wv);
    __shared__ float t[32][33];
    int tx = threadIdx.x, ty = threadIdx.y;
    int n0 = blockIdx.x * 32, k0 = blockIdx.y * 32;
    #pragma unroll
    for (int r = 0; r < 4; r++) {
        int k = k0 + ty + r * 8;
        t[ty + r * 8][tx] = W[(size_t)k * DD + n0 + tx];
    }
    __syncthreads();
    #pragma unroll
    for (int r = 0; r < 4; r++) {
        int nn = n0 + ty + r * 8;
        int kk = k0 + tx;
        float v = t[tx][ty + r * 8];
        __half hi = __float2half(v);
        __half lo = __float2half(v - __half2float(hi));
        g_wh[z][(size_t)nn * DD + kk] = hi;
        g_wl[z][(size_t)nn * DD + kk] = lo;
    }
}

// ---------------------------------------------------------------------------
// QKV GEMM via fp16 mma.sync, 2-term (x single * W pair).
// CTA 128x128, 8 warps (2Mx4N), warp tile 64x32, K-chunk 32, 3 stages.
// 3 arrays/stage (X, Wh, Wl) x 8 KB = 24 KB/stage -> 72 KB -> 2 CTAs/SM.
// ---------------------------------------------------------------------------
#define GT2   (128 * 32)
#define NSTG  3
#define GSMB  (NSTG * 3 * GT2 * 2)

__device__ __forceinline__ uint32_t gsw(int row, int chunk) {
    return (uint32_t)(row * 64 + ((chunk ^ ((row >> 1) & 3)) << 4));
}

__global__ __launch_bounds__(256, 2) void qkv_gemm_mma(
    const float* __restrict__ bq, const float* __restrict__ bk, const float* __restrict__ bv)
{
    extern __shared__ __half gsm[];

    const int tid  = threadIdx.x;
    const int lane = tid & 31;
    const int wid  = tid >> 5;
    const int wm   = wid >> 2;
    const int wn   = wid & 3;
    const int z    = blockIdx.z;
    const int m0   = blockIdx.y * 128;
    const int n0   = blockIdx.x * 128;

    const __half* __restrict__ gA  = g_x;
    const __half* __restrict__ gBh = g_wh[z];
    const __half* __restrict__ gBl = g_wl[z];
    const float* bias = z == 0 ? bq : (z == 1 ? bk : bv);

    const uint32_t sb = smem_u32(gsm);

    float acc[4][4][4];
    #pragma unroll
    for (int mt = 0; mt < 4; mt++)
        #pragma unroll
        for (int nt = 0; nt < 4; nt++)
            #pragma unroll
            for (int r = 0; r < 4; r++) acc[mt][nt][r] = 0.f;

    const int fr = lane >> 2;
    const int fc = (lane & 3) * 2;

    auto issue_chunk = [&](int c) {
        const uint32_t base = sb + (uint32_t)((c % NSTG) * 3 * GT2) * 2;
        const int k0 = c * 32;
        #pragma unroll
        for (int i = 0; i < 2; i++) {
            const int idx = tid + i * 256;
            const int row = idx >> 2;
            const int seg = idx & 3;
            const uint32_t doff = gsw(row, seg);
            const size_t ao = (size_t)(m0 + row) * DD + k0 + seg * 8;
            const size_t bo = (size_t)(n0 + row) * DD + k0 + seg * 8;
            cp16(base + 0u * GT2 * 2 + doff, gA  + ao);
            cp16(base + 1u * GT2 * 2 + doff, gBh + bo);
            cp16(base + 2u * GT2 * 2 + doff, gBl + bo);
        }
        CP_COMMIT();
    };

    issue_chunk(0);
    issue_chunk(1);

    for (int c = 0; c < 32; c++) {
        if (c < 30) asm volatile("cp.async.wait_group 1;" ::: "memory");
        else        asm volatile("cp.async.wait_group 0;" ::: "memory");
        __syncthreads();

        const uint32_t sbase = sb + (uint32_t)((c % NSTG) * 3 * GT2) * 2;
        #pragma unroll
        for (int ks = 0; ks < 2; ks++) {
            const int kc = ks * 2;
            uint32_t a[4][4], bh[4][2], bl[4][2];
            #pragma unroll
            for (int mt = 0; mt < 4; mt++) {
                const int row = wm * 64 + mt * 16 + (lane & 15);
                const uint32_t aoff = gsw(row, kc + (lane >> 4));
                ldm_x4(a[mt][0], a[mt][1], a[mt][2], a[mt][3],
                       sbase + 0u * GT2 * 2 + aoff);
            }
            #pragma unroll
            for (int np = 0; np < 2; np++) {
                const int row = wn * 32 + np * 16 + (lane & 7) + ((lane >> 4) << 3);
                const uint32_t boff = gsw(row, kc + ((lane >> 3) & 1));
                ldm_x4(bh[np * 2][0], bh[np * 2][1], bh[np * 2 + 1][0], bh[np * 2 + 1][1],
                       sbase + 1u * GT2 * 2 + boff);
                ldm_x4(bl[np * 2][0], bl[np * 2][1], bl[np * 2 + 1][0], bl[np * 2 + 1][1],
                       sbase + 2u * GT2 * 2 + boff);
            }
            #pragma unroll
            for (int mt = 0; mt < 4; mt++)
                #pragma unroll
                for (int nt = 0; nt < 4; nt++)
                    mma16816(acc[mt][nt][0], acc[mt][nt][1], acc[mt][nt][2], acc[mt][nt][3],
                             a[mt][0], a[mt][1], a[mt][2], a[mt][3],
                             bh[nt][0], bh[nt][1]);
            #pragma unroll
            for (int mt = 0; mt < 4; mt++)
                #pragma unroll
                for (int nt = 0; nt < 4; nt++)
                    mma16816(acc[mt][nt][0], acc[mt][nt][1], acc[mt][nt][2], acc[mt][nt][3],
                             a[mt][0], a[mt][1], a[mt][2], a[mt][3],
                             bl[nt][0], bl[nt][1]);
        }

        if (c + 2 < 32) issue_chunk(c + 2);
    }

    const float sc = (z == 0) ? SCQ : 1.0f;

    #pragma unroll
    for (int nt = 0; nt < 4; nt++) {
        const int n = n0 + wn * 32 + nt * 8 + fc;
        const int h = n >> 6;
        const int hd = n & 63;
        const float bv0 = bias[n];
        const float bv1 = bias[n + 1];
        #pragma unroll
        for (int mt = 0; mt < 4; mt++) {
            #pragma unroll
            for (int half = 0; half < 2; half++) {
                const int m = m0 + wm * 64 + mt * 16 + fr + half * 8;
                const int bb = m >> 10;
                const int s = m & 1023;
                float v0 = (acc[mt][nt][half * 2 + 0] + bv0) * sc;
                float v1 = (acc[mt][nt][half * 2 + 1] + bv1) * sc;
                size_t idx = ((size_t)(bb * HH + h) * SS + s) * HD + hd;
                if (z == 0) {
                    __half h0 = __float2half(v0), h1 = __float2half(v1);
                    __half2 hv; hv.x = h0; hv.y = h1;
                    __half2 lv = __floats2half2_rn(
                        v0 - __half2float(h0), v1 - __half2float(h1));
                    *(__half2*)(g_qh + idx) = hv;
                    *(__half2*)(g_ql + idx) = lv;
                } else if (z == 1) {
                    *(__half2*)(g_k + idx) = __floats2half2_rn(v0, v1);
                } else {
                    const size_t tb = (size_t)(bb * HH + h) * HD;
                    __half h0 = __float2half(v0);
                    __half l0 = __float2half(v0 - __half2float(h0));
                    __half h1 = __float2half(v1);
                    __half l1 = __float2half(v1 - __half2float(h1));
                    g_vth[(tb + hd) * SS + s]     = h0;
                    g_vtl[(tb + hd) * SS + s]     = l0;
                    g_vth[(tb + hd + 1) * SS + s] = h1;
                    g_vtl[(tb + hd + 1) * SS + s] = l1;
                }
            }
        }
    }
}

// ---------------------------------------------------------------------------
// Pack adj into 1-bit mask and copy adj to second output region.
// ---------------------------------------------------------------------------
__global__ __launch_bounds__(256) void mask_pack(
    const float* __restrict__ adj, float* __restrict__ adj_out)
{
    int w = blockIdx.x * blockDim.x + threadIdx.x;
    const float4* a4 = (const float4*)adj;
    float4* o4 = (float4*)adj_out;
    unsigned bits = 0;
    #pragma unroll
    for (int i = 0; i < 8; i++) {
        float4 v = a4[(size_t)w * 8 + i];
        o4[(size_t)w * 8 + i] = v;
        bits |= (v.x >= 0.5f ? 1u : 0u) << (i * 4 + 0);
        bits |= (v.y >= 0.5f ? 1u : 0u) << (i * 4 + 1);
        bits |= (v.z >= 0.5f ? 1u : 0u) << (i * 4 + 2);
        bits |= (v.w >= 0.5f ? 1u : 0u) << (i * 4 + 3);
    }
    g_mask[w] = bits;
}

// ---------------------------------------------------------------------------
// Flash attention: fp16 2-term. S = (Q pair)(K single); O = (P single)(V pair).
// q-tile 128, 256 threads, ldmatrix, K/V double-buffered. No-max softmax.
// SMEM: Q pair 36.9 KB + 2 stages x 3 arrays x 9.2 KB = 92 KB -> 2 CTAs/SM.
// ---------------------------------------------------------------------------
#define AQP 72
#define KT_ELEM (64 * AQP)
#define QT_ELEM (128 * AQP)
#define ATT_SMEM ((2 * QT_ELEM + 2 * 3 * KT_ELEM) * 2)

__global__ __launch_bounds__(256, 2) void attn_mma(float* __restrict__ out)
{
    extern __shared__ __half smp[];
    __half* Qh = smp;
    __half* Ql = Qh + QT_ELEM;
    __half* KV = Ql + QT_ELEM;         // 2 stages x {K, Vh, Vl}

    const int tid  = threadIdx.x;
    const int lane = tid & 31;
    const int warp = tid >> 5;
    const int g    = lane >> 2;
    const int t    = lane & 3;
    const int q0   = blockIdx.x * 128;
    const int h    = blockIdx.y;
    const int bb   = blockIdx.z;
    const int wq0  = warp * 16;

    const size_t bhs = ((size_t)(bb * HH + h)) * SS;
    const __half* gqh = g_qh + (bhs + q0) * HD;
    const __half* gql = g_ql + (bhs + q0) * HD;
    const __half* gk  = g_k + bhs * HD;
    const __half* gvh = g_vth + ((size_t)(bb * HH + h)) * HD * SS;
    const __half* gvl = g_vtl + ((size_t)(bb * HH + h)) * HD * SS;

    const uint32_t sQh = smem_u32(Qh);
    const uint32_t sQl = smem_u32(Ql);
    const uint32_t sKV = smem_u32(KV);

    {
        #pragma unroll
        for (int j = 0; j < 4; j++) {
            int id  = tid + j * 256;
            int r   = id >> 3;
            int seg = id & 7;
            uint32_t doff = (uint32_t)(r * AQP + seg * 8) * 2;
            cp16(sQh + doff, gqh + (size_t)r * HD + seg * 8);
            cp16(sQl + doff, gql + (size_t)r * HD + seg * 8);
        }
        #pragma unroll
        for (int j = 0; j < 2; j++) {
            int id  = tid + j * 256;
            int r   = id >> 3;
            int seg = id & 7;
            uint32_t doff = (uint32_t)(r * AQP + seg * 8) * 2;
            cp16(sKV + 0 * KT_ELEM * 2 + doff, gk  + (size_t)r * HD + seg * 8);
            cp16(sKV + 1 * KT_ELEM * 2 + doff, gvh + (size_t)r * SS + seg * 8);
            cp16(sKV + 2 * KT_ELEM * 2 + doff, gvl + (size_t)r * SS + seg * 8);
        }
        CP_COMMIT();
    }

    float o_acc[8][4];
    #pragma unroll
    for (int nt = 0; nt < 8; nt++)
        #pragma unroll
        for (int e = 0; e < 4; e++) o_acc[nt][e] = 0.f;
    float l0v = 0.f, l1v = 0.f;

    const unsigned* mrow = g_mask + (size_t)bb * SS * (SS / 32);
    const int r0g = q0 + wq0 + g;
    const int r1g = r0g + 8;

    const uint32_t a_row  = (uint32_t)(wq0 + (lane & 15));
    const uint32_t a_cofs = (uint32_t)((lane >> 4) << 3);
    const uint32_t b_rofs = (uint32_t)((lane & 7) + ((lane >> 4) << 3));
    const uint32_t b_cofs = (uint32_t)(((lane >> 3) & 1) << 3);

    for (int kt = 0; kt < 16; kt++) {
        const int cur = kt & 1;
        if (kt + 1 < 16) {
            const int nxt = (kt + 1) & 1;
            const uint32_t base = sKV + (uint32_t)(nxt * 3 * KT_ELEM) * 2;
            const size_t koff = (size_t)(kt + 1) * 64;
            #pragma unroll
            for (int j = 0; j < 2; j++) {
                int id  = tid + j * 256;
                int r   = id >> 3;
                int seg = id & 7;
                uint32_t doff = (uint32_t)(r * AQP + seg * 8) * 2;
                cp16(base + 0 * KT_ELEM * 2 + doff, gk  + (koff + r) * HD + seg * 8);
                cp16(base + 1 * KT_ELEM * 2 + doff, gvh + (size_t)r * SS + koff + seg * 8);
                cp16(base + 2 * KT_ELEM * 2 + doff, gvl + (size_t)r * SS + koff + seg * 8);
            }
            CP_COMMIT();
            asm volatile("cp.async.wait_group 1;" ::: "memory");
        } else {
            asm volatile("cp.async.wait_group 0;" ::: "memory");
        }
        __syncthreads();

        const uint32_t sK  = sKV + (uint32_t)((cur * 3 + 0) * KT_ELEM) * 2;
        const uint32_t sVh = sKV + (uint32_t)((cur * 3 + 1) * KT_ELEM) * 2;
        const uint32_t sVl = sKV + (uint32_t)((cur * 3 + 2) * KT_ELEM) * 2;

        // ---- S = Q K^T:  (qh + ql) x k ----
        float sf[8][4];
        #pragma unroll
        for (int nt = 0; nt < 8; nt++)
            #pragma unroll
            for (int e = 0; e < 4; e++) sf[nt][e] = 0.f;

        #pragma unroll
        for (int kk = 0; kk < 4; kk++) {
            const uint32_t kb = kk * 16;
            uint32_t qah[4], qal[4];
            const uint32_t aoff = (a_row * AQP + kb + a_cofs) * 2;
            ldm_x4(qah[0], qah[1], qah[2], qah[3], sQh + aoff);
            ldm_x4(qal[0], qal[1], qal[2], qal[3], sQl + aoff);
            #pragma unroll
            for (int np = 0; np < 4; np++) {
                uint32_t k0r, k1r, k2r, k3r;
                const uint32_t boff = ((np * 16 + b_rofs) * AQP + kb + b_cofs) * 2;
                ldm_x4(k0r, k1r, k2r, k3r, sK + boff);
                float* d0 = sf[np * 2];
                float* d1 = sf[np * 2 + 1];
                mma16816(d0[0], d0[1], d0[2], d0[3], qah[0], qah[1], qah[2], qah[3], k0r, k1r);
                mma16816(d1[0], d1[1], d1[2], d1[3], qah[0], qah[1], qah[2], qah[3], k2r, k3r);
                mma16816(d0[0], d0[1], d0[2], d0[3], qal[0], qal[1], qal[2], qal[3], k0r, k1r);
                mma16816(d1[0], d1[1], d1[2], d1[3], qal[0], qal[1], qal[2], qal[3], k2r, k3r);
            }
        }

        // ---- mask + exp2 (no max), pack P to single fp16 ----
        const unsigned w0 = mrow[(size_t)r0g * 32 + kt * 2];
        const unsigned w1 = mrow[(size_t)r0g * 32 + kt * 2 + 1];
        const unsigned w2 = mrow[(size_t)r1g * 32 + kt * 2];
        const unsigned w3 = mrow[(size_t)r1g * 32 + kt * 2 + 1];

        uint32_t ph0[8], ph1[8];
        #pragma unroll
        for (int nt = 0; nt < 8; nt++) {
            const unsigned wa = nt < 4 ? w0 : w1;
            const unsigned wb = nt < 4 ? w2 : w3;
            const int sh = (nt & 3) * 8 + 2 * t;
            float p00 = exp2f(sf[nt][0] + (((wa >> sh) & 1u) ? 0.f : NEGV));
            float p01 = exp2f(sf[nt][1] + (((wa >> (sh + 1)) & 1u) ? 0.f : NEGV));
            float p10 = exp2f(sf[nt][2] + (((wb >> sh) & 1u) ? 0.f : NEGV));
            float p11 = exp2f(sf[nt][3] + (((wb >> (sh + 1)) & 1u) ? 0.f : NEGV));
            l0v += p00 + p01;
            l1v += p10 + p11;
            __half2 hv0 = __floats2half2_rn(p00, p01);
            __half2 hv1 = __floats2half2_rn(p10, p11);
            ph0[nt] = *(uint32_t*)&hv0;
            ph1[nt] = *(uint32_t*)&hv1;
        }

        // ---- O += P V:  p x (vh + vl) ----
        #pragma unroll
        for (int kc = 0; kc < 4; kc++) {
            const uint32_t pa0 = ph0[2 * kc],     pa1 = ph1[2 * kc];
            const uint32_t pa2 = ph0[2 * kc + 1], pa3 = ph1[2 * kc + 1];
            #pragma unroll
            for (int np = 0; np < 4; np++) {
                uint32_t vh0, vh1, vh2, vh3, vl0, vl1, vl2, vl3;
                const uint32_t boff = ((np * 16 + b_rofs) * AQP + kc * 16 + b_cofs) * 2;
                ldm_x4(vh0, vh1, vh2, vh3, sVh + boff);
                ldm_x4(vl0, vl1, vl2, vl3, sVl + boff);
                float* d0 = o_acc[np * 2];
                float* d1 = o_acc[np * 2 + 1];
                mma16816(d0[0], d0[1], d0[2], d0[3], pa0, pa1, pa2, pa3, vh0, vh1);
                mma16816(d1[0], d1[1], d1[2], d1[3], pa0, pa1, pa2, pa3, vh2, vh3);
                mma16816(d0[0], d0[1], d0[2], d0[3], pa0, pa1, pa2, pa3, vl0, vl1);
                mma16816(d1[0], d1[1], d1[2], d1[3], pa0, pa1, pa2, pa3, vl2, vl3);
            }
        }
        __syncthreads();
    }

    l0v += __shfl_xor_sync(0xffffffffu, l0v, 1);
    l0v += __shfl_xor_sync(0xffffffffu, l0v, 2);
    l1v += __shfl_xor_sync(0xffffffffu, l1v, 1);
    l1v += __shfl_xor_sync(0xffffffffu, l1v, 2);
    const float inv0 = 1.f / l0v;
    const float inv1 = 1.f / l1v;
    #pragma unroll
    for (int nt = 0; nt < 8; nt++) {
        const int col = h * 64 + nt * 8 + 2 * t;
        float2 oa, ob;
        oa.x = fmaxf(o_acc[nt][0] * inv0, 0.f);
        oa.y = fmaxf(o_acc[nt][1] * inv0, 0.f);
        ob.x = fmaxf(o_acc[nt][2] * inv1, 0.f);
        ob.y = fmaxf(o_acc[nt][3] * inv1, 0.f);
        *(float2*)(out + ((size_t)bb * SS + r0g) * DD + col) = oa;
        *(float2*)(out + ((size_t)bb * SS + r1g) * DD + col) = ob;
    }
}

// ---------------------------------------------------------------------------
// Launch: fork/join side stream (conv_w + mask_pack overlap GEMM).
// ---------------------------------------------------------------------------
extern "C" void kernel_launch(void* const* d_in, const int* in_sizes, int n_in,
                              void* d_out, int out_size)
{
    const float* x   = (const float*)d_in[0];
    const float* adj = (const float*)d_in[1];
    const float* Wq  = (const float*)d_in[2];
    const float* bq  = (const float*)d_in[3];
    const float* Wk  = (const float*)d_in[4];
    const float* bk  = (const float*)d_in[5];
    const float* Wv  = (const float*)d_in[6];
    const float* bv  = (const float*)d_in[7];

    float* out     = (float*)d_out;
    float* out_adj = out + (size_t)BB * SS * DD;

    static cudaStream_t side = nullptr;
    static cudaEvent_t evF = nullptr, evW = nullptr, evM = nullptr;
    static bool attrs_set = false;
    if (side == nullptr) {
        cudaStreamCreateWithFlags(&side, cudaStreamNonBlocking);
        cudaEventCreateWithFlags(&evF, cudaEventDisableTiming);
        cudaEventCreateWithFlags(&evW, cudaEventDisableTiming);
        cudaEventCreateWithFlags(&evM, cudaEventDisableTiming);
    }
    if (!attrs_set) {
        cudaFuncSetAttribute(qkv_gemm_mma, cudaFuncAttributeMaxDynamicSharedMemorySize, GSMB);
        cudaFuncSetAttribute(attn_mma, cudaFuncAttributeMaxDynamicSharedMemorySize, ATT_SMEM);
        attrs_set = true;
    }

    cudaEventRecord(evF, 0);
    cudaStreamWaitEvent(side, evF, 0);

    conv_w<<<dim3(DD / 32, DD / 32, 3), dim3(32, 8), 0, side>>>(Wq, Wk, Wv);
    cudaEventRecord(evW, side);
    mask_pack<<<(BB * SS * (SS / 32)) / 256, 256, 0, side>>>(adj, out_adj);
    cudaEventRecord(evM, side);

    conv_x<<<(BB * SS * DD) / (256 * 4), 256>>>(x);
    cudaStreamWaitEvent(0, evW, 0);
    qkv_gemm_mma<<<dim3(DD / 128, (BB * SS) / 128, 3), 256, GSMB>>>(bq, bk, bv);
    cudaStreamWaitEvent(0, evM, 0);
    attn_mma<<<dim3(SS / 128, HH, BB), 256, ATT_SMEM>>>(out);
}

// round 16
// speedup vs baseline: 1.8228x; 1.2028x over previous
#include <cuda_runtime.h>
#include <cuda_fp16.h>
#include <cstdint>

#define BB 4
#define SS 1024
#define DD 1024
#define HH 16
#define HD 64
#define NEGV -10000000.0f
#define SCQ 0.18033688011112042f   /* 0.125 * log2(e) */

// ---------------------------------------------------------------------------
// Scratch (__device__ globals; no allocation allowed)
// ---------------------------------------------------------------------------
__device__ unsigned g_mask[BB*SS*(SS/32)];
__device__ __half g_x[BB*SS*DD];              // x, single fp16
__device__ __half g_w[3][DD*DD];              // W transposed [n][k], single fp16
__device__ __half g_qh[BB*HH*SS*HD];          // Q pair (pre-scaled by SCQ)
__device__ __half g_ql[BB*HH*SS*HD];
__device__ __half g_k[BB*HH*SS*HD];           // K single
__device__ __half g_vth[BB*HH*HD*SS];         // V^T pair [b,h,hd,s]
__device__ __half g_vtl[BB*HH*HD*SS];

// ---------------------------------------------------------------------------
// PTX helpers (baseline PTX only — works on plain sm_103 target)
// ---------------------------------------------------------------------------
__device__ __forceinline__ void mma16816(
    float& d0, float& d1, float& d2, float& d3,
    uint32_t a0, uint32_t a1, uint32_t a2, uint32_t a3,
    uint32_t b0, uint32_t b1)
{
    asm volatile(
        "mma.sync.aligned.m16n8k16.row.col.f32.f16.f16.f32 "
        "{%0,%1,%2,%3}, {%4,%5,%6,%7}, {%8,%9}, {%0,%1,%2,%3};"
        : "+f"(d0), "+f"(d1), "+f"(d2), "+f"(d3)
        : "r"(a0), "r"(a1), "r"(a2), "r"(a3), "r"(b0), "r"(b1));
}

__device__ __forceinline__ void ldm_x4(
    uint32_t& r0, uint32_t& r1, uint32_t& r2, uint32_t& r3, uint32_t addr)
{
    asm volatile("ldmatrix.sync.aligned.m8n8.x4.shared.b16 {%0,%1,%2,%3}, [%4];"
        : "=r"(r0), "=r"(r1), "=r"(r2), "=r"(r3) : "r"(addr));
}

__device__ __forceinline__ uint32_t smem_u32(const void* p) {
    uint32_t a;
    asm("{ .reg .u64 t; cvta.to.shared.u64 t, %1; cvt.u32.u64 %0, t; }"
        : "=r"(a) : "l"(p));
    return a;
}

__device__ __forceinline__ void cp16(uint32_t dst, const void* src) {
    asm volatile("cp.async.cg.shared.global [%0], [%1], 16;" :: "r"(dst), "l"(src));
}
#define CP_COMMIT() asm volatile("cp.async.commit_group;" ::: "memory")

// ---------------------------------------------------------------------------
// Prep: x -> single fp16
// ---------------------------------------------------------------------------
__global__ __launch_bounds__(256) void conv_x(const float* __restrict__ x)
{
    size_t i = ((size_t)blockIdx.x * 256 + threadIdx.x) * 4;
    float4 v = *(const float4*)(x + i);
    __half2 a = __floats2half2_rn(v.x, v.y);
    __half2 b = __floats2half2_rn(v.z, v.w);
    *(__half2*)(g_x + i)     = a;
    *(__half2*)(g_x + i + 2) = b;
}

// ---------------------------------------------------------------------------
// Prep: transpose W [K,N] -> Wt [N,K], single fp16
// ---------------------------------------------------------------------------
__global__ __launch_bounds__(256) void conv_w(
    const float* __restrict__ Wq, const float* __restrict__ Wk, const float* __restrict__ Wv)
{
    const int z = blockIdx.z;
    const float* W = z == 0 ? Wq : (z == 1 ? Wk : Wv);
    __shared__ float t[32][33];
    int tx = threadIdx.x, ty = threadIdx.y;
    int n0 = blockIdx.x * 32, k0 = blockIdx.y * 32;
    #pragma unroll
    for (int r = 0; r < 4; r++) {
        int k = k0 + ty + r * 8;
        t[ty + r * 8][tx] = W[(size_t)k * DD + n0 + tx];
    }
    __syncthreads();
    #pragma unroll
    for (int r = 0; r < 4; r++) {
        int nn = n0 + ty + r * 8;
        int kk = k0 + tx;
        g_w[z][(size_t)nn * DD + kk] = __float2half(t[tx][ty + r * 8]);
    }
}

// ---------------------------------------------------------------------------
// QKV GEMM via fp16 mma.sync, single-term (x single * W single).
// CTA 128x128, 8 warps (2Mx4N), warp tile 64x32, K-chunk 32, 3 stages.
// 2 arrays/stage (X, W) x 8 KB = 16 KB/stage -> 48 KB -> 2 CTAs/SM (reg-bound).
// ---------------------------------------------------------------------------
#define GT2   (128 * 32)
#define NSTG  3
#define GSMB  (NSTG * 2 * GT2 * 2)

__device__ __forceinline__ uint32_t gsw(int row, int chunk) {
    return (uint32_t)(row * 64 + ((chunk ^ ((row >> 1) & 3)) << 4));
}

__global__ __launch_bounds__(256, 2) void qkv_gemm_mma(
    const float* __restrict__ bq, const float* __restrict__ bk, const float* __restrict__ bv)
{
    extern __shared__ __half gsm[];

    const int tid  = threadIdx.x;
    const int lane = tid & 31;
    const int wid  = tid >> 5;
    const int wm   = wid >> 2;
    const int wn   = wid & 3;
    const int z    = blockIdx.z;
    const int m0   = blockIdx.y * 128;
    const int n0   = blockIdx.x * 128;

    const __half* __restrict__ gA = g_x;
    const __half* __restrict__ gB = g_w[z];
    const float* bias = z == 0 ? bq : (z == 1 ? bk : bv);

    const uint32_t sb = smem_u32(gsm);

    float acc[4][4][4];
    #pragma unroll
    for (int mt = 0; mt < 4; mt++)
        #pragma unroll
        for (int nt = 0; nt < 4; nt++)
            #pragma unroll
            for (int r = 0; r < 4; r++) acc[mt][nt][r] = 0.f;

    const int fr = lane >> 2;
    const int fc = (lane & 3) * 2;

    auto issue_chunk = [&](int c) {
        const uint32_t base = sb + (uint32_t)((c % NSTG) * 2 * GT2) * 2;
        const int k0 = c * 32;
        #pragma unroll
        for (int i = 0; i < 2; i++) {
            const int idx = tid + i * 256;
            const int row = idx >> 2;
            const int seg = idx & 3;
            const uint32_t doff = gsw(row, seg);
            cp16(base + 0u * GT2 * 2 + doff, gA + (size_t)(m0 + row) * DD + k0 + seg * 8);
            cp16(base + 1u * GT2 * 2 + doff, gB + (size_t)(n0 + row) * DD + k0 + seg * 8);
        }
        CP_COMMIT();
    };

    issue_chunk(0);
    issue_chunk(1);

    for (int c = 0; c < 32; c++) {
        if (c < 30) asm volatile("cp.async.wait_group 1;" ::: "memory");
        else        asm volatile("cp.async.wait_group 0;" ::: "memory");
        __syncthreads();

        const uint32_t sbase = sb + (uint32_t)((c % NSTG) * 2 * GT2) * 2;
        #pragma unroll
        for (int ks = 0; ks < 2; ks++) {
            const int kc = ks * 2;
            uint32_t a[4][4], b[4][2];
            #pragma unroll
            for (int mt = 0; mt < 4; mt++) {
                const int row = wm * 64 + mt * 16 + (lane & 15);
                const uint32_t aoff = gsw(row, kc + (lane >> 4));
                ldm_x4(a[mt][0], a[mt][1], a[mt][2], a[mt][3],
                       sbase + 0u * GT2 * 2 + aoff);
            }
            #pragma unroll
            for (int np = 0; np < 2; np++) {
                const int row = wn * 32 + np * 16 + (lane & 7) + ((lane >> 4) << 3);
                const uint32_t boff = gsw(row, kc + ((lane >> 3) & 1));
                ldm_x4(b[np * 2][0], b[np * 2][1], b[np * 2 + 1][0], b[np * 2 + 1][1],
                       sbase + 1u * GT2 * 2 + boff);
            }
            #pragma unroll
            for (int mt = 0; mt < 4; mt++)
                #pragma unroll
                for (int nt = 0; nt < 4; nt++)
                    mma16816(acc[mt][nt][0], acc[mt][nt][1], acc[mt][nt][2], acc[mt][nt][3],
                             a[mt][0], a[mt][1], a[mt][2], a[mt][3],
                             b[nt][0], b[nt][1]);
        }

        if (c + 2 < 32) issue_chunk(c + 2);
    }

    const float sc = (z == 0) ? SCQ : 1.0f;

    #pragma unroll
    for (int nt = 0; nt < 4; nt++) {
        const int n = n0 + wn * 32 + nt * 8 + fc;
        const int h = n >> 6;
        const int hd = n & 63;
        const float bv0 = bias[n];
        const float bv1 = bias[n + 1];
        #pragma unroll
        for (int mt = 0; mt < 4; mt++) {
            #pragma unroll
            for (int half = 0; half < 2; half++) {
                const int m = m0 + wm * 64 + mt * 16 + fr + half * 8;
                const int bb = m >> 10;
                const int s = m & 1023;
                float v0 = (acc[mt][nt][half * 2 + 0] + bv0) * sc;
                float v1 = (acc[mt][nt][half * 2 + 1] + bv1) * sc;
                size_t idx = ((size_t)(bb * HH + h) * SS + s) * HD + hd;
                if (z == 0) {
                    __half h0 = __float2half(v0), h1 = __float2half(v1);
                    __half2 hv; hv.x = h0; hv.y = h1;
                    __half2 lv = __floats2half2_rn(
                        v0 - __half2float(h0), v1 - __half2float(h1));
                    *(__half2*)(g_qh + idx) = hv;
                    *(__half2*)(g_ql + idx) = lv;
                } else if (z == 1) {
                    *(__half2*)(g_k + idx) = __floats2half2_rn(v0, v1);
                } else {
                    const size_t tb = (size_t)(bb * HH + h) * HD;
                    __half h0 = __float2half(v0);
                    __half l0 = __float2half(v0 - __half2float(h0));
                    __half h1 = __float2half(v1);
                    __half l1 = __float2half(v1 - __half2float(h1));
                    g_vth[(tb + hd) * SS + s]     = h0;
                    g_vtl[(tb + hd) * SS + s]     = l0;
                    g_vth[(tb + hd + 1) * SS + s] = h1;
                    g_vtl[(tb + hd + 1) * SS + s] = l1;
                }
            }
        }
    }
}

// ---------------------------------------------------------------------------
// Pack adj into 1-bit mask and copy adj to second output region.
// ---------------------------------------------------------------------------
__global__ __launch_bounds__(256) void mask_pack(
    const float* __restrict__ adj, float* __restrict__ adj_out)
{
    int w = blockIdx.x * blockDim.x + threadIdx.x;
    const float4* a4 = (const float4*)adj;
    float4* o4 = (float4*)adj_out;
    unsigned bits = 0;
    #pragma unroll
    for (int i = 0; i < 8; i++) {
        float4 v = a4[(size_t)w * 8 + i];
        o4[(size_t)w * 8 + i] = v;
        bits |= (v.x >= 0.5f ? 1u : 0u) << (i * 4 + 0);
        bits |= (v.y >= 0.5f ? 1u : 0u) << (i * 4 + 1);
        bits |= (v.z >= 0.5f ? 1u : 0u) << (i * 4 + 2);
        bits |= (v.w >= 0.5f ? 1u : 0u) << (i * 4 + 3);
    }
    g_mask[w] = bits;
}

// ---------------------------------------------------------------------------
// Flash attention: fp16. S = (Q pair)(K single); O = (P single)(V pair).
// q-tile 128, 256 threads, ldmatrix, K/V double-buffered. No-max softmax.
// ---------------------------------------------------------------------------
#define AQP 72
#define KT_ELEM (64 * AQP)
#define QT_ELEM (128 * AQP)
#define ATT_SMEM ((2 * QT_ELEM + 2 * 3 * KT_ELEM) * 2)

__global__ __launch_bounds__(256, 2) void attn_mma(float* __restrict__ out)
{
    extern __shared__ __half smp[];
    __half* Qh = smp;
    __half* Ql = Qh + QT_ELEM;
    __half* KV = Ql + QT_ELEM;         // 2 stages x {K, Vh, Vl}

    const int tid  = threadIdx.x;
    const int lane = tid & 31;
    const int warp = tid >> 5;
    const int g    = lane >> 2;
    const int t    = lane & 3;
    const int q0   = blockIdx.x * 128;
    const int h    = blockIdx.y;
    const int bb   = blockIdx.z;
    const int wq0  = warp * 16;

    const size_t bhs = ((size_t)(bb * HH + h)) * SS;
    const __half* gqh = g_qh + (bhs + q0) * HD;
    const __half* gql = g_ql + (bhs + q0) * HD;
    const __half* gk  = g_k + bhs * HD;
    const __half* gvh = g_vth + ((size_t)(bb * HH + h)) * HD * SS;
    const __half* gvl = g_vtl + ((size_t)(bb * HH + h)) * HD * SS;

    const uint32_t sQh = smem_u32(Qh);
    const uint32_t sQl = smem_u32(Ql);
    const uint32_t sKV = smem_u32(KV);

    {
        #pragma unroll
        for (int j = 0; j < 4; j++) {
            int id  = tid + j * 256;
            int r   = id >> 3;
            int seg = id & 7;
            uint32_t doff = (uint32_t)(r * AQP + seg * 8) * 2;
            cp16(sQh + doff, gqh + (size_t)r * HD + seg * 8);
            cp16(sQl + doff, gql + (size_t)r * HD + seg * 8);
        }
        #pragma unroll
        for (int j = 0; j < 2; j++) {
            int id  = tid + j * 256;
            int r   = id >> 3;
            int seg = id & 7;
            uint32_t doff = (uint32_t)(r * AQP + seg * 8) * 2;
            cp16(sKV + 0 * KT_ELEM * 2 + doff, gk  + (size_t)r * HD + seg * 8);
            cp16(sKV + 1 * KT_ELEM * 2 + doff, gvh + (size_t)r * SS + seg * 8);
            cp16(sKV + 2 * KT_ELEM * 2 + doff, gvl + (size_t)r * SS + seg * 8);
        }
        CP_COMMIT();
    }

    float o_acc[8][4];
    #pragma unroll
    for (int nt = 0; nt < 8; nt++)
        #pragma unroll
        for (int e = 0; e < 4; e++) o_acc[nt][e] = 0.f;
    float l0v = 0.f, l1v = 0.f;

    const unsigned* mrow = g_mask + (size_t)bb * SS * (SS / 32);
    const int r0g = q0 + wq0 + g;
    const int r1g = r0g + 8;

    const uint32_t a_row  = (uint32_t)(wq0 + (lane & 15));
    const uint32_t a_cofs = (uint32_t)((lane >> 4) << 3);
    const uint32_t b_rofs = (uint32_t)((lane & 7) + ((lane >> 4) << 3));
    const uint32_t b_cofs = (uint32_t)(((lane >> 3) & 1) << 3);

    for (int kt = 0; kt < 16; kt++) {
        const int cur = kt & 1;
        if (kt + 1 < 16) {
            const int nxt = (kt + 1) & 1;
            const uint32_t base = sKV + (uint32_t)(nxt * 3 * KT_ELEM) * 2;
            const size_t koff = (size_t)(kt + 1) * 64;
            #pragma unroll
            for (int j = 0; j < 2; j++) {
                int id  = tid + j * 256;
                int r   = id >> 3;
                int seg = id & 7;
                uint32_t doff = (uint32_t)(r * AQP + seg * 8) * 2;
                cp16(base + 0 * KT_ELEM * 2 + doff, gk  + (koff + r) * HD + seg * 8);
                cp16(base + 1 * KT_ELEM * 2 + doff, gvh + (size_t)r * SS + koff + seg * 8);
                cp16(base + 2 * KT_ELEM * 2 + doff, gvl + (size_t)r * SS + koff + seg * 8);
            }
            CP_COMMIT();
            asm volatile("cp.async.wait_group 1;" ::: "memory");
        } else {
            asm volatile("cp.async.wait_group 0;" ::: "memory");
        }
        __syncthreads();

        const uint32_t sK  = sKV + (uint32_t)((cur * 3 + 0) * KT_ELEM) * 2;
        const uint32_t sVh = sKV + (uint32_t)((cur * 3 + 1) * KT_ELEM) * 2;
        const uint32_t sVl = sKV + (uint32_t)((cur * 3 + 2) * KT_ELEM) * 2;

        // ---- S = Q K^T:  (qh + ql) x k ----
        float sf[8][4];
        #pragma unroll
        for (int nt = 0; nt < 8; nt++)
            #pragma unroll
            for (int e = 0; e < 4; e++) sf[nt][e] = 0.f;

        #pragma unroll
        for (int kk = 0; kk < 4; kk++) {
            const uint32_t kb = kk * 16;
            uint32_t qah[4], qal[4];
            const uint32_t aoff = (a_row * AQP + kb + a_cofs) * 2;
            ldm_x4(qah[0], qah[1], qah[2], qah[3], sQh + aoff);
            ldm_x4(qal[0], qal[1], qal[2], qal[3], sQl + aoff);
            #pragma unroll
            for (int np = 0; np < 4; np++) {
                uint32_t k0r, k1r, k2r, k3r;
                const uint32_t boff = ((np * 16 + b_rofs) * AQP + kb + b_cofs) * 2;
                ldm_x4(k0r, k1r, k2r, k3r, sK + boff);
                float* d0 = sf[np * 2];
                float* d1 = sf[np * 2 + 1];
                mma16816(d0[0], d0[1], d0[2], d0[3], qah[0], qah[1], qah[2], qah[3], k0r, k1r);
                mma16816(d1[0], d1[1], d1[2], d1[3], qah[0], qah[1], qah[2], qah[3], k2r, k3r);
                mma16816(d0[0], d0[1], d0[2], d0[3], qal[0], qal[1], qal[2], qal[3], k0r, k1r);
                mma16816(d1[0], d1[1], d1[2], d1[3], qal[0], qal[1], qal[2], qal[3], k2r, k3r);
            }
        }

        // ---- mask + exp2 (no max), pack P to single fp16 ----
        const unsigned w0 = mrow[(size_t)r0g * 32 + kt * 2];
        const unsigned w1 = mrow[(size_t)r0g * 32 + kt * 2 + 1];
        const unsigned w2 = mrow[(size_t)r1g * 32 + kt * 2];
        const unsigned w3 = mrow[(size_t)r1g * 32 + kt * 2 + 1];

        uint32_t ph0[8], ph1[8];
        #pragma unroll
        for (int nt = 0; nt < 8; nt++) {
            const unsigned wa = nt < 4 ? w0 : w1;
            const unsigned wb = nt < 4 ? w2 : w3;
            const int sh = (nt & 3) * 8 + 2 * t;
            float p00 = exp2f(sf[nt][0] + (((wa >> sh) & 1u) ? 0.f : NEGV));
            float p01 = exp2f(sf[nt][1] + (((wa >> (sh + 1)) & 1u) ? 0.f : NEGV));
            float p10 = exp2f(sf[nt][2] + (((wb >> sh) & 1u) ? 0.f : NEGV));
            float p11 = exp2f(sf[nt][3] + (((wb >> (sh + 1)) & 1u) ? 0.f : NEGV));
            l0v += p00 + p01;
            l1v += p10 + p11;
            __half2 hv0 = __floats2half2_rn(p00, p01);
            __half2 hv1 = __floats2half2_rn(p10, p11);
            ph0[nt] = *(uint32_t*)&hv0;
            ph1[nt] = *(uint32_t*)&hv1;
        }

        // ---- O += P V:  p x (vh + vl) ----
        #pragma unroll
        for (int kc = 0; kc < 4; kc++) {
            const uint32_t pa0 = ph0[2 * kc],     pa1 = ph1[2 * kc];
            const uint32_t pa2 = ph0[2 * kc + 1], pa3 = ph1[2 * kc + 1];
            #pragma unroll
            for (int np = 0; np < 4; np++) {
                uint32_t vh0, vh1, vh2, vh3, vl0, vl1, vl2, vl3;
                const uint32_t boff = ((np * 16 + b_rofs) * AQP + kc * 16 + b_cofs) * 2;
                ldm_x4(vh0, vh1, vh2, vh3, sVh + boff);
                ldm_x4(vl0, vl1, vl2, vl3, sVl + boff);
                float* d0 = o_acc[np * 2];
                float* d1 = o_acc[np * 2 + 1];
                mma16816(d0[0], d0[1], d0[2], d0[3], pa0, pa1, pa2, pa3, vh0, vh1);
                mma16816(d1[0], d1[1], d1[2], d1[3], pa0, pa1, pa2, pa3, vh2, vh3);
                mma16816(d0[0], d0[1], d0[2], d0[3], pa0, pa1, pa2, pa3, vl0, vl1);
                mma16816(d1[0], d1[1], d1[2], d1[3], pa0, pa1, pa2, pa3, vl2, vl3);
            }
        }
        __syncthreads();
    }

    l0v += __shfl_xor_sync(0xffffffffu, l0v, 1);
    l0v += __shfl_xor_sync(0xffffffffu, l0v, 2);
    l1v += __shfl_xor_sync(0xffffffffu, l1v, 1);
    l1v += __shfl_xor_sync(0xffffffffu, l1v, 2);
    const float inv0 = 1.f / l0v;
    const float inv1 = 1.f / l1v;
    #pragma unroll
    for (int nt = 0; nt < 8; nt++) {
        const int col = h * 64 + nt * 8 + 2 * t;
        float2 oa, ob;
        oa.x = fmaxf(o_acc[nt][0] * inv0, 0.f);
        oa.y = fmaxf(o_acc[nt][1] * inv0, 0.f);
        ob.x = fmaxf(o_acc[nt][2] * inv1, 0.f);
        ob.y = fmaxf(o_acc[nt][3] * inv1, 0.f);
        *(float2*)(out + ((size_t)bb * SS + r0g) * DD + col) = oa;
        *(float2*)(out + ((size_t)bb * SS + r1g) * DD + col) = ob;
    }
}

// ---------------------------------------------------------------------------
// Launch: fork/join side stream (conv_w + mask_pack overlap GEMM).
// ---------------------------------------------------------------------------
extern "C" void kernel_launch(void* const* d_in, const int* in_sizes, int n_in,
                              void* d_out, int out_size)
{
    const float* x   = (const float*)d_in[0];
    const float* adj = (const float*)d_in[1];
    const float* Wq  = (const float*)d_in[2];
    const float* bq  = (const float*)d_in[3];
    const float* Wk  = (const float*)d_in[4];
    const float* bk  = (const float*)d_in[5];
    const float* Wv  = (const float*)d_in[6];
    const float* bv  = (const float*)d_in[7];

    float* out     = (float*)d_out;
    float* out_adj = out + (size_t)BB * SS * DD;

    static cudaStream_t side = nullptr;
    static cudaEvent_t evF = nullptr, evW = nullptr, evM = nullptr;
    static bool attrs_set = false;
    if (side == nullptr) {
        cudaStreamCreateWithFlags(&side, cudaStreamNonBlocking);
        cudaEventCreateWithFlags(&evF, cudaEventDisableTiming);
        cudaEventCreateWithFlags(&evW, cudaEventDisableTiming);
        cudaEventCreateWithFlags(&evM, cudaEventDisableTiming);
    }
    if (!attrs_set) {
        cudaFuncSetAttribute(qkv_gemm_mma, cudaFuncAttributeMaxDynamicSharedMemorySize, GSMB);
        cudaFuncSetAttribute(attn_mma, cudaFuncAttributeMaxDynamicSharedMemorySize, ATT_SMEM);
        attrs_set = true;
    }

    cudaEventRecord(evF, 0);
    cudaStreamWaitEvent(side, evF, 0);

    conv_w<<<dim3(DD / 32, DD / 32, 3), dim3(32, 8), 0, side>>>(Wq, Wk, Wv);
    cudaEventRecord(evW, side);
    mask_pack<<<(BB * SS * (SS / 32)) / 256, 256, 0, side>>>(adj, out_adj);
    cudaEventRecord(evM, side);

    conv_x<<<(BB * SS * DD) / (256 * 4), 256>>>(x);
    cudaStreamWaitEvent(0, evW, 0);
    qkv_gemm_mma<<<dim3(DD / 128, (BB * SS) / 128, 3), 256, GSMB>>>(bq, bk, bv);
    cudaStreamWaitEvent(0, evM, 0);
    attn_mma<<<dim3(SS / 128, HH, BB), 256, ATT_SMEM>>>(out);
}

// round 17
// speedup vs baseline: 2.0159x; 1.1059x over previous
#include <cuda_runtime.h>
#include <cuda_fp16.h>
#include <cstdint>

#define BB 4
#define SS 1024
#define DD 1024
#define HH 16
#define HD 64
#define NEGV -10000000.0f
#define SCQ 0.18033688011112042f   /* 0.125 * log2(e) */

// ---------------------------------------------------------------------------
// Scratch (__device__ globals; no allocation allowed)
// ---------------------------------------------------------------------------
__device__ unsigned g_mask[BB*SS*(SS/32)];
__device__ __half g_x[BB*SS*DD];              // x, single fp16
__device__ __half g_w[3][DD*DD];              // W transposed [n][k], single fp16
__device__ __half g_q[BB*HH*SS*HD];           // Q single (pre-scaled by SCQ)
__device__ __half g_k[BB*HH*SS*HD];           // K single
__device__ __half g_vth[BB*HH*HD*SS];         // V^T pair [b,h,hd,s]
__device__ __half g_vtl[BB*HH*HD*SS];

// ---------------------------------------------------------------------------
// PTX helpers (baseline PTX only — works on plain sm_103 target)
// ---------------------------------------------------------------------------
__device__ __forceinline__ void mma16816(
    float& d0, float& d1, float& d2, float& d3,
    uint32_t a0, uint32_t a1, uint32_t a2, uint32_t a3,
    uint32_t b0, uint32_t b1)
{
    asm volatile(
        "mma.sync.aligned.m16n8k16.row.col.f32.f16.f16.f32 "
        "{%0,%1,%2,%3}, {%4,%5,%6,%7}, {%8,%9}, {%0,%1,%2,%3};"
        : "+f"(d0), "+f"(d1), "+f"(d2), "+f"(d3)
        : "r"(a0), "r"(a1), "r"(a2), "r"(a3), "r"(b0), "r"(b1));
}

__device__ __forceinline__ void ldm_x4(
    uint32_t& r0, uint32_t& r1, uint32_t& r2, uint32_t& r3, uint32_t addr)
{
    asm volatile("ldmatrix.sync.aligned.m8n8.x4.shared.b16 {%0,%1,%2,%3}, [%4];"
        : "=r"(r0), "=r"(r1), "=r"(r2), "=r"(r3) : "r"(addr));
}

__device__ __forceinline__ uint32_t smem_u32(const void* p) {
    uint32_t a;
    asm("{ .reg .u64 t; cvta.to.shared.u64 t, %1; cvt.u32.u64 %0, t; }"
        : "=r"(a) : "l"(p));
    return a;
}

__device__ __forceinline__ void cp16(uint32_t dst, const void* src) {
    asm volatile("cp.async.cg.shared.global [%0], [%1], 16;" :: "r"(dst), "l"(src));
}
#define CP_COMMIT() asm volatile("cp.async.commit_group;" ::: "memory")

// ---------------------------------------------------------------------------
// Prep: x -> single fp16
// ---------------------------------------------------------------------------
__global__ __launch_bounds__(256) void conv_x(const float* __restrict__ x)
{
    size_t i = ((size_t)blockIdx.x * 256 + threadIdx.x) * 4;
    float4 v = *(const float4*)(x + i);
    *(__half2*)(g_x + i)     = __floats2half2_rn(v.x, v.y);
    *(__half2*)(g_x + i + 2) = __floats2half2_rn(v.z, v.w);
}

// ---------------------------------------------------------------------------
// Prep: transpose W [K,N] -> Wt [N,K], single fp16
// ---------------------------------------------------------------------------
__global__ __launch_bounds__(256) void conv_w(
    const float* __restrict__ Wq, const float* __restrict__ Wk, const float* __restrict__ Wv)
{
    const int z = blockIdx.z;
    const float* W = z == 0 ? Wq : (z == 1 ? Wk : Wv);
    __shared__ float t[32][33];
    int tx = threadIdx.x, ty = threadIdx.y;
    int n0 = blockIdx.x * 32, k0 = blockIdx.y * 32;
    #pragma unroll
    for (int r = 0; r < 4; r++) {
        int k = k0 + ty + r * 8;
        t[ty + r * 8][tx] = W[(size_t)k * DD + n0 + tx];
    }
    __syncthreads();
    #pragma unroll
    for (int r = 0; r < 4; r++) {
        int nn = n0 + ty + r * 8;
        int kk = k0 + tx;
        g_w[z][(size_t)nn * DD + kk] = __float2half(t[tx][ty + r * 8]);
    }
}

// ---------------------------------------------------------------------------
// QKV GEMM via fp16 mma.sync, single-term, K-chunk 64.
// CTA 128x128, 8 warps (2Mx4N), warp tile 64x32, 3 stages.
// Stage: 2 arrays (X, W) x 128 rows x 64 halves (128 B/row, full swizzle).
// 3 x 32 KB = 96 KB -> 2 CTAs/SM.
// ---------------------------------------------------------------------------
#define GT3   (128 * 64)
#define NSTG  3
#define GSMB  (NSTG * 2 * GT3 * 2)

__device__ __forceinline__ uint32_t gsw64(int row, int chunk) {
    return (uint32_t)(row * 128 + ((chunk ^ (row & 7)) << 4));
}

__global__ __launch_bounds__(256, 2) void qkv_gemm_mma(
    const float* __restrict__ bq, const float* __restrict__ bk, const float* __restrict__ bv)
{
    extern __shared__ __half gsm[];

    const int tid  = threadIdx.x;
    const int lane = tid & 31;
    const int wid  = tid >> 5;
    const int wm   = wid >> 2;
    const int wn   = wid & 3;
    const int z    = blockIdx.z;
    const int m0   = blockIdx.y * 128;
    const int n0   = blockIdx.x * 128;

    const __half* __restrict__ gA = g_x;
    const __half* __restrict__ gB = g_w[z];
    const float* bias = z == 0 ? bq : (z == 1 ? bk : bv);

    const uint32_t sb = smem_u32(gsm);

    float acc[4][4][4];
    #pragma unroll
    for (int mt = 0; mt < 4; mt++)
        #pragma unroll
        for (int nt = 0; nt < 4; nt++)
            #pragma unroll
            for (int r = 0; r < 4; r++) acc[mt][nt][r] = 0.f;

    const int fr = lane >> 2;
    const int fc = (lane & 3) * 2;

    auto issue_chunk = [&](int c) {
        const uint32_t base = sb + (uint32_t)((c % NSTG) * 2 * GT3) * 2;
        const int k0 = c * 64;
        #pragma unroll
        for (int i = 0; i < 4; i++) {
            const int idx = tid + i * 256;       // 0..1023
            const int row = idx >> 3;            // 0..127
            const int seg = idx & 7;             // 0..7
            const uint32_t doff = gsw64(row, seg);
            cp16(base + 0u * GT3 * 2 + doff, gA + (size_t)(m0 + row) * DD + k0 + seg * 8);
            cp16(base + 1u * GT3 * 2 + doff, gB + (size_t)(n0 + row) * DD + k0 + seg * 8);
        }
        CP_COMMIT();
    };

    issue_chunk(0);
    issue_chunk(1);

    for (int c = 0; c < 16; c++) {
        if (c < 14) asm volatile("cp.async.wait_group 1;" ::: "memory");
        else        asm volatile("cp.async.wait_group 0;" ::: "memory");
        __syncthreads();

        const uint32_t sbase = sb + (uint32_t)((c % NSTG) * 2 * GT3) * 2;
        #pragma unroll
        for (int ks = 0; ks < 4; ks++) {
            const int kc = ks * 2;
            uint32_t a[4][4], b[4][2];
            #pragma unroll
            for (int mt = 0; mt < 4; mt++) {
                const int row = wm * 64 + mt * 16 + (lane & 15);
                const uint32_t aoff = gsw64(row, kc + (lane >> 4));
                ldm_x4(a[mt][0], a[mt][1], a[mt][2], a[mt][3],
                       sbase + 0u * GT3 * 2 + aoff);
            }
            #pragma unroll
            for (int np = 0; np < 2; np++) {
                const int row = wn * 32 + np * 16 + (lane & 7) + ((lane >> 4) << 3);
                const uint32_t boff = gsw64(row, kc + ((lane >> 3) & 1));
                ldm_x4(b[np * 2][0], b[np * 2][1], b[np * 2 + 1][0], b[np * 2 + 1][1],
                       sbase + 1u * GT3 * 2 + boff);
            }
            #pragma unroll
            for (int mt = 0; mt < 4; mt++)
                #pragma unroll
                for (int nt = 0; nt < 4; nt++)
                    mma16816(acc[mt][nt][0], acc[mt][nt][1], acc[mt][nt][2], acc[mt][nt][3],
                             a[mt][0], a[mt][1], a[mt][2], a[mt][3],
                             b[nt][0], b[nt][1]);
        }

        if (c + 2 < 16) issue_chunk(c + 2);
    }

    const float sc = (z == 0) ? SCQ : 1.0f;

    #pragma unroll
    for (int nt = 0; nt < 4; nt++) {
        const int n = n0 + wn * 32 + nt * 8 + fc;
        const int h = n >> 6;
        const int hd = n & 63;
        const float bv0 = bias[n];
        const float bv1 = bias[n + 1];
        #pragma unroll
        for (int mt = 0; mt < 4; mt++) {
            #pragma unroll
            for (int half = 0; half < 2; half++) {
                const int m = m0 + wm * 64 + mt * 16 + fr + half * 8;
                const int bb = m >> 10;
                const int s = m & 1023;
                float v0 = (acc[mt][nt][half * 2 + 0] + bv0) * sc;
                float v1 = (acc[mt][nt][half * 2 + 1] + bv1) * sc;
                size_t idx = ((size_t)(bb * HH + h) * SS + s) * HD + hd;
                if (z == 0) {
                    *(__half2*)(g_q + idx) = __floats2half2_rn(v0, v1);
                } else if (z == 1) {
                    *(__half2*)(g_k + idx) = __floats2half2_rn(v0, v1);
                } else {
                    const size_t tb = (size_t)(bb * HH + h) * HD;
                    __half h0 = __float2half(v0);
                    __half l0 = __float2half(v0 - __half2float(h0));
                    __half h1 = __float2half(v1);
                    __half l1 = __float2half(v1 - __half2float(h1));
                    g_vth[(tb + hd) * SS + s]     = h0;
                    g_vtl[(tb + hd) * SS + s]     = l0;
                    g_vth[(tb + hd + 1) * SS + s] = h1;
                    g_vtl[(tb + hd + 1) * SS + s] = l1;
                }
            }
        }
    }
}

// ---------------------------------------------------------------------------
// Pack adj into 1-bit mask and copy adj to second output region.
// ---------------------------------------------------------------------------
__global__ __launch_bounds__(256) void mask_pack(
    const float* __restrict__ adj, float* __restrict__ adj_out)
{
    int w = blockIdx.x * blockDim.x + threadIdx.x;
    const float4* a4 = (const float4*)adj;
    float4* o4 = (float4*)adj_out;
    unsigned bits = 0;
    #pragma unroll
    for (int i = 0; i < 8; i++) {
        float4 v = a4[(size_t)w * 8 + i];
        o4[(size_t)w * 8 + i] = v;
        bits |= (v.x >= 0.5f ? 1u : 0u) << (i * 4 + 0);
        bits |= (v.y >= 0.5f ? 1u : 0u) << (i * 4 + 1);
        bits |= (v.z >= 0.5f ? 1u : 0u) << (i * 4 + 2);
        bits |= (v.w >= 0.5f ? 1u : 0u) << (i * 4 + 3);
    }
    g_mask[w] = bits;
}

// ---------------------------------------------------------------------------
// Flash attention: fp16. S = (Q single)(K single); O = (P single)(V pair).
// q-tile 128, 256 threads, ldmatrix, K/V double-buffered. No-max softmax.
// SMEM: Q 18.4 KB + 2 stages x 3 x 9.2 KB = 73.7 KB -> 2 CTAs/SM.
// ---------------------------------------------------------------------------
#define AQP 72
#define KT_ELEM (64 * AQP)
#define QT_ELEM (128 * AQP)
#define ATT_SMEM ((QT_ELEM + 2 * 3 * KT_ELEM) * 2)

__global__ __launch_bounds__(256, 2) void attn_mma(float* __restrict__ out)
{
    extern __shared__ __half smp[];
    __half* Qs = smp;
    __half* KV = Qs + QT_ELEM;         // 2 stages x {K, Vh, Vl}

    const int tid  = threadIdx.x;
    const int lane = tid & 31;
    const int warp = tid >> 5;
    const int g    = lane >> 2;
    const int t    = lane & 3;
    const int q0   = blockIdx.x * 128;
    const int h    = blockIdx.y;
    const int bb   = blockIdx.z;
    const int wq0  = warp * 16;

    const size_t bhs = ((size_t)(bb * HH + h)) * SS;
    const __half* gq  = g_q + (bhs + q0) * HD;
    const __half* gk  = g_k + bhs * HD;
    const __half* gvh = g_vth + ((size_t)(bb * HH + h)) * HD * SS;
    const __half* gvl = g_vtl + ((size_t)(bb * HH + h)) * HD * SS;

    const uint32_t sQ  = smem_u32(Qs);
    const uint32_t sKV = smem_u32(KV);

    {
        #pragma unroll
        for (int j = 0; j < 4; j++) {
            int id  = tid + j * 256;          // 0..1023
            int r   = id >> 3;
            int seg = id & 7;
            uint32_t doff = (uint32_t)(r * AQP + seg * 8) * 2;
            cp16(sQ + doff, gq + (size_t)r * HD + seg * 8);
        }
        #pragma unroll
        for (int j = 0; j < 2; j++) {
            int id  = tid + j * 256;
            int r   = id >> 3;
            int seg = id & 7;
            uint32_t doff = (uint32_t)(r * AQP + seg * 8) * 2;
            cp16(sKV + 0 * KT_ELEM * 2 + doff, gk  + (size_t)r * HD + seg * 8);
            cp16(sKV + 1 * KT_ELEM * 2 + doff, gvh + (size_t)r * SS + seg * 8);
            cp16(sKV + 2 * KT_ELEM * 2 + doff, gvl + (size_t)r * SS + seg * 8);
        }
        CP_COMMIT();
    }

    float o_acc[8][4];
    #pragma unroll
    for (int nt = 0; nt < 8; nt++)
        #pragma unroll
        for (int e = 0; e < 4; e++) o_acc[nt][e] = 0.f;
    float l0v = 0.f, l1v = 0.f;

    const unsigned* mrow = g_mask + (size_t)bb * SS * (SS / 32);
    const int r0g = q0 + wq0 + g;
    const int r1g = r0g + 8;

    const uint32_t a_row  = (uint32_t)(wq0 + (lane & 15));
    const uint32_t a_cofs = (uint32_t)((lane >> 4) << 3);
    const uint32_t b_rofs = (uint32_t)((lane & 7) + ((lane >> 4) << 3));
    const uint32_t b_cofs = (uint32_t)(((lane >> 3) & 1) << 3);

    for (int kt = 0; kt < 16; kt++) {
        const int cur = kt & 1;
        if (kt + 1 < 16) {
            const int nxt = (kt + 1) & 1;
            const uint32_t base = sKV + (uint32_t)(nxt * 3 * KT_ELEM) * 2;
            const size_t koff = (size_t)(kt + 1) * 64;
            #pragma unroll
            for (int j = 0; j < 2; j++) {
                int id  = tid + j * 256;
                int r   = id >> 3;
                int seg = id & 7;
                uint32_t doff = (uint32_t)(r * AQP + seg * 8) * 2;
                cp16(base + 0 * KT_ELEM * 2 + doff, gk  + (koff + r) * HD + seg * 8);
                cp16(base + 1 * KT_ELEM * 2 + doff, gvh + (size_t)r * SS + koff + seg * 8);
                cp16(base + 2 * KT_ELEM * 2 + doff, gvl + (size_t)r * SS + koff + seg * 8);
            }
            CP_COMMIT();
            asm volatile("cp.async.wait_group 1;" ::: "memory");
        } else {
            asm volatile("cp.async.wait_group 0;" ::: "memory");
        }
        __syncthreads();

        const uint32_t sK  = sKV + (uint32_t)((cur * 3 + 0) * KT_ELEM) * 2;
        const uint32_t sVh = sKV + (uint32_t)((cur * 3 + 1) * KT_ELEM) * 2;
        const uint32_t sVl = sKV + (uint32_t)((cur * 3 + 2) * KT_ELEM) * 2;

        // ---- S = Q K^T (single x single) ----
        float sf[8][4];
        #pragma unroll
        for (int nt = 0; nt < 8; nt++)
            #pragma unroll
            for (int e = 0; e < 4; e++) sf[nt][e] = 0.f;

        #pragma unroll
        for (int kk = 0; kk < 4; kk++) {
            const uint32_t kb = kk * 16;
            uint32_t qa[4];
            const uint32_t aoff = (a_row * AQP + kb + a_cofs) * 2;
            ldm_x4(qa[0], qa[1], qa[2], qa[3], sQ + aoff);
            #pragma unroll
            for (int np = 0; np < 4; np++) {
                uint32_t k0r, k1r, k2r, k3r;
                const uint32_t boff = ((np * 16 + b_rofs) * AQP + kb + b_cofs) * 2;
                ldm_x4(k0r, k1r, k2r, k3r, sK + boff);
                float* d0 = sf[np * 2];
                float* d1 = sf[np * 2 + 1];
                mma16816(d0[0], d0[1], d0[2], d0[3], qa[0], qa[1], qa[2], qa[3], k0r, k1r);
                mma16816(d1[0], d1[1], d1[2], d1[3], qa[0], qa[1], qa[2], qa[3], k2r, k3r);
            }
        }

        // ---- mask + exp2 (no max), pack P to single fp16 ----
        const unsigned w0 = mrow[(size_t)r0g * 32 + kt * 2];
        const unsigned w1 = mrow[(size_t)r0g * 32 + kt * 2 + 1];
        const unsigned w2 = mrow[(size_t)r1g * 32 + kt * 2];
        const unsigned w3 = mrow[(size_t)r1g * 32 + kt * 2 + 1];

        uint32_t ph0[8], ph1[8];
        #pragma unroll
        for (int nt = 0; nt < 8; nt++) {
            const unsigned wa = nt < 4 ? w0 : w1;
            const unsigned wb = nt < 4 ? w2 : w3;
            const int sh = (nt & 3) * 8 + 2 * t;
            float p00 = exp2f(sf[nt][0] + (((wa >> sh) & 1u) ? 0.f : NEGV));
            float p01 = exp2f(sf[nt][1] + (((wa >> (sh + 1)) & 1u) ? 0.f : NEGV));
            float p10 = exp2f(sf[nt][2] + (((wb >> sh) & 1u) ? 0.f : NEGV));
            float p11 = exp2f(sf[nt][3] + (((wb >> (sh + 1)) & 1u) ? 0.f : NEGV));
            l0v += p00 + p01;
            l1v += p10 + p11;
            __half2 hv0 = __floats2half2_rn(p00, p01);
            __half2 hv1 = __floats2half2_rn(p10, p11);
            ph0[nt] = *(uint32_t*)&hv0;
            ph1[nt] = *(uint32_t*)&hv1;
        }

        // ---- O += P V:  p x (vh + vl) ----
        #pragma unroll
        for (int kc = 0; kc < 4; kc++) {
            const uint32_t pa0 = ph0[2 * kc],     pa1 = ph1[2 * kc];
            const uint32_t pa2 = ph0[2 * kc + 1], pa3 = ph1[2 * kc + 1];
            #pragma unroll
            for (int np = 0; np < 4; np++) {
                uint32_t vh0, vh1, vh2, vh3, vl0, vl1, vl2, vl3;
                const uint32_t boff = ((np * 16 + b_rofs) * AQP + kc * 16 + b_cofs) * 2;
                ldm_x4(vh0, vh1, vh2, vh3, sVh + boff);
                ldm_x4(vl0, vl1, vl2, vl3, sVl + boff);
                float* d0 = o_acc[np * 2];
                float* d1 = o_acc[np * 2 + 1];
                mma16816(d0[0], d0[1], d0[2], d0[3], pa0, pa1, pa2, pa3, vh0, vh1);
                mma16816(d1[0], d1[1], d1[2], d1[3], pa0, pa1, pa2, pa3, vh2, vh3);
                mma16816(d0[0], d0[1], d0[2], d0[3], pa0, pa1, pa2, pa3, vl0, vl1);
                mma16816(d1[0], d1[1], d1[2], d1[3], pa0, pa1, pa2, pa3, vl2, vl3);
            }
        }
        __syncthreads();
    }

    l0v += __shfl_xor_sync(0xffffffffu, l0v, 1);
    l0v += __shfl_xor_sync(0xffffffffu, l0v, 2);
    l1v += __shfl_xor_sync(0xffffffffu, l1v, 1);
    l1v += __shfl_xor_sync(0xffffffffu, l1v, 2);
    const float inv0 = 1.f / l0v;
    const float inv1 = 1.f / l1v;
    #pragma unroll
    for (int nt = 0; nt < 8; nt++) {
        const int col = h * 64 + nt * 8 + 2 * t;
        float2 oa, ob;
        oa.x = fmaxf(o_acc[nt][0] * inv0, 0.f);
        oa.y = fmaxf(o_acc[nt][1] * inv0, 0.f);
        ob.x = fmaxf(o_acc[nt][2] * inv1, 0.f);
        ob.y = fmaxf(o_acc[nt][3] * inv1, 0.f);
        *(float2*)(out + ((size_t)bb * SS + r0g) * DD + col) = oa;
        *(float2*)(out + ((size_t)bb * SS + r1g) * DD + col) = ob;
    }
}

// ---------------------------------------------------------------------------
// Launch: fork/join side stream (conv_w + mask_pack overlap GEMM).
// ---------------------------------------------------------------------------
extern "C" void kernel_launch(void* const* d_in, const int* in_sizes, int n_in,
                              void* d_out, int out_size)
{
    const float* x   = (const float*)d_in[0];
    const float* adj = (const float*)d_in[1];
    const float* Wq  = (const float*)d_in[2];
    const float* bq  = (const float*)d_in[3];
    const float* Wk  = (const float*)d_in[4];
    const float* bk  = (const float*)d_in[5];
    const float* Wv  = (const float*)d_in[6];
    const float* bv  = (const float*)d_in[7];

    float* out     = (float*)d_out;
    float* out_adj = out + (size_t)BB * SS * DD;

    static cudaStream_t side = nullptr;
    static cudaEvent_t evF = nullptr, evW = nullptr, evM = nullptr;
    static bool attrs_set = false;
    if (side == nullptr) {
        cudaStreamCreateWithFlags(&side, cudaStreamNonBlocking);
        cudaEventCreateWithFlags(&evF, cudaEventDisableTiming);
        cudaEventCreateWithFlags(&evW, cudaEventDisableTiming);
        cudaEventCreateWithFlags(&evM, cudaEventDisableTiming);
    }
    if (!attrs_set) {
        cudaFuncSetAttribute(qkv_gemm_mma, cudaFuncAttributeMaxDynamicSharedMemorySize, GSMB);
        cudaFuncSetAttribute(attn_mma, cudaFuncAttributeMaxDynamicSharedMemorySize, ATT_SMEM);
        attrs_set = true;
    }

    cudaEventRecord(evF, 0);
    cudaStreamWaitEvent(side, evF, 0);

    conv_w<<<dim3(DD / 32, DD / 32, 3), dim3(32, 8), 0, side>>>(Wq, Wk, Wv);
    cudaEventRecord(evW, side);
    mask_pack<<<(BB * SS * (SS / 32)) / 256, 256, 0, side>>>(adj, out_adj);
    cudaEventRecord(evM, side);

    conv_x<<<(BB * SS * DD) / (256 * 4), 256>>>(x);
    cudaStreamWaitEvent(0, evW, 0);
    qkv_gemm_mma<<<dim3(DD / 128, (BB * SS) / 128, 3), 256, GSMB>>>(bq, bk, bv);
    cudaStreamWaitEvent(0, evM, 0);
    attn_mma<<<dim3(SS / 128, HH, BB), 256, ATT_SMEM>>>(out);
}